// round 2
// baseline (speedup 1.0000x reference)
#include <cuda_runtime.h>

#define N_NODES 100000
#define N_EDGES 1600000
#define FEAT 128
#define N_GRAPHS 100
#define SA 132  // smem row stride (floats), %4==0 for 16B-aligned float4 reads

// Scratch (allocation-free rule: __device__ globals)
__device__ float g_bufA[(size_t)N_NODES * FEAT];
__device__ float g_bufB[(size_t)N_NODES * FEAT];
__device__ int g_idx64;  // 1 if edge_index/batch are int64, 0 if int32

// ---------------------------------------------------------------------------
// Index dtype detector: if edge_index is little-endian int64 with values in
// [0, N_NODES), every odd int32 word is 0 and every even word is in range.
// For genuine int32 node ids, 512 consecutive odd words all being zero has
// probability ~(1/N_NODES)^512 ~= 0.
// ---------------------------------------------------------------------------
__global__ void detect_kernel(const int* __restrict__ ei_words) {
    int is64 = 1;
    for (int i = 0; i < 512; i++) {
        int lo = ei_words[2 * i];
        int hi = ei_words[2 * i + 1];
        if (hi != 0 || lo < 0 || lo >= N_NODES) { is64 = 0; break; }
    }
    g_idx64 = is64;
}

// ---------------------------------------------------------------------------
// float4 copy: dst = src
// ---------------------------------------------------------------------------
__global__ void copy_kernel(const float* __restrict__ src, float* __restrict__ dst, int n4) {
    int i = blockIdx.x * blockDim.x + threadIdx.x;
    if (i < n4) ((float4*)dst)[i] = ((const float4*)src)[i];
}

// ---------------------------------------------------------------------------
// GIN aggregation scatter: dst_feat[dst_row] += src_feat[src_row] per edge.
// One warp per edge, one float4 per lane (32*4 = 128 feats).
// ---------------------------------------------------------------------------
__global__ void scatter_kernel(const float* __restrict__ src_feat,
                               float* __restrict__ dst_feat,
                               const void* __restrict__ ei) {
    long long t = (long long)blockIdx.x * blockDim.x + threadIdx.x;
    int e = (int)(t >> 5);
    if (e >= N_EDGES) return;
    int l = (int)(t & 31);
    long long s, d;
    if (g_idx64) {
        const long long* e64 = (const long long*)ei;
        s = e64[e];
        d = e64[(long long)N_EDGES + e];
    } else {
        const int* e32 = (const int*)ei;
        s = e32[e];
        d = e32[N_EDGES + e];
    }
    float4 v = ((const float4*)(src_feat + s * FEAT))[l];
    float* dp = dst_feat + d * FEAT + (l << 2);
    atomicAdd(dp + 0, v.x);
    atomicAdd(dp + 1, v.y);
    atomicAdd(dp + 2, v.z);
    atomicAdd(dp + 3, v.w);
}

// ---------------------------------------------------------------------------
// C[m][n] = relu( sum_k A[m][k] * W[n][k] + bias[n] )
// A: [M][128] row-major, W: [128][128] row-major (out,in), C: [M][128].
// Block tile 128(M) x 128(N), K=128 fully resident in smem.
// 256 threads, 8x8 microtile per thread.
// Both A-tile and W are stored k-major in smem (transposed on load) so the
// mainloop fragment loads are float4 + broadcast, conflict-free.
// ---------------------------------------------------------------------------
__global__ void gemm_bias_relu_kernel(const float* __restrict__ A,
                                      const float* __restrict__ W,
                                      const float* __restrict__ bias,
                                      float* __restrict__ C, int M) {
    extern __shared__ float sm[];
    float* As = sm;              // As[k*SA + m] = A[row0+m][k]
    float* Bs = sm + 128 * SA;   // Bs[k*SA + n] = W[n][k]

    const int tid = threadIdx.x;
    const int row0 = blockIdx.x * 128;

    {
        const int m = tid & 127;
        const int c0 = tid >> 7;  // 0 or 1
        const int gr = row0 + m;
        const bool in = (gr < M);
        const float4* arow = (const float4*)(A + (size_t)gr * FEAT);
        const float4* wrow = (const float4*)(W + (size_t)m * FEAT);
#pragma unroll
        for (int j = 0; j < 16; j++) {
            const int c = c0 + 2 * j;       // float4 index along k: 0..31
            const int k = 4 * c;
            float4 va = in ? arow[c] : make_float4(0.f, 0.f, 0.f, 0.f);
            As[(k + 0) * SA + m] = va.x;
            As[(k + 1) * SA + m] = va.y;
            As[(k + 2) * SA + m] = va.z;
            As[(k + 3) * SA + m] = va.w;
            float4 vw = wrow[c];
            Bs[(k + 0) * SA + m] = vw.x;
            Bs[(k + 1) * SA + m] = vw.y;
            Bs[(k + 2) * SA + m] = vw.z;
            Bs[(k + 3) * SA + m] = vw.w;
        }
    }
    __syncthreads();

    const int tx = tid & 15;   // n-dim: cols 8*tx .. 8*tx+7
    const int ty = tid >> 4;   // m-dim: rows 8*ty .. 8*ty+7

    float acc[8][8];
#pragma unroll
    for (int i = 0; i < 8; i++)
#pragma unroll
        for (int j = 0; j < 8; j++) acc[i][j] = 0.f;

#pragma unroll 8
    for (int k = 0; k < 128; k++) {
        const float* ap = As + k * SA + 8 * ty;
        const float* bp = Bs + k * SA + 8 * tx;
        float4 a0 = *(const float4*)(ap);
        float4 a1 = *(const float4*)(ap + 4);
        float4 b0 = *(const float4*)(bp);
        float4 b1 = *(const float4*)(bp + 4);
        float a[8] = {a0.x, a0.y, a0.z, a0.w, a1.x, a1.y, a1.z, a1.w};
        float b[8] = {b0.x, b0.y, b0.z, b0.w, b1.x, b1.y, b1.z, b1.w};
#pragma unroll
        for (int i = 0; i < 8; i++)
#pragma unroll
            for (int j = 0; j < 8; j++) acc[i][j] += a[i] * b[j];
    }

    float bv[8];
#pragma unroll
    for (int j = 0; j < 8; j++) bv[j] = bias[8 * tx + j];

#pragma unroll
    for (int i = 0; i < 8; i++) {
        const int m = row0 + 8 * ty + i;
        if (m < M) {
            float4 o0, o1;
            o0.x = fmaxf(acc[i][0] + bv[0], 0.f);
            o0.y = fmaxf(acc[i][1] + bv[1], 0.f);
            o0.z = fmaxf(acc[i][2] + bv[2], 0.f);
            o0.w = fmaxf(acc[i][3] + bv[3], 0.f);
            o1.x = fmaxf(acc[i][4] + bv[4], 0.f);
            o1.y = fmaxf(acc[i][5] + bv[5], 0.f);
            o1.z = fmaxf(acc[i][6] + bv[6], 0.f);
            o1.w = fmaxf(acc[i][7] + bv[7], 0.f);
            float* crow = C + (size_t)m * FEAT + 8 * tx;
            *(float4*)(crow) = o0;
            *(float4*)(crow + 4) = o1;
        }
    }
}

// ---------------------------------------------------------------------------
// Global mean pool per graph. batch is SORTED, so each block binary-searches
// its graph's [start,end) node range and column-sums with coalesced reads.
// ---------------------------------------------------------------------------
__global__ void pool_kernel(const float* __restrict__ h,
                            const void* __restrict__ batch,
                            float* __restrict__ out_pool) {
    const int g = blockIdx.x;
    const int c = threadIdx.x;  // 0..127
    const int is64 = g_idx64;
    const long long* b64 = (const long long*)batch;
    const int* b32 = (const int*)batch;

    int lo = 0, hi = N_NODES;
    while (lo < hi) {
        int mid = (lo + hi) >> 1;
        long long v = is64 ? b64[mid] : (long long)b32[mid];
        if (v < (long long)g) lo = mid + 1; else hi = mid;
    }
    const int start = lo;
    hi = N_NODES;
    while (lo < hi) {
        int mid = (lo + hi) >> 1;
        long long v = is64 ? b64[mid] : (long long)b32[mid];
        if (v < (long long)g + 1) lo = mid + 1; else hi = mid;
    }
    const int end = lo;

    float s = 0.f;
    for (int r = start; r < end; r++) s += h[(size_t)r * FEAT + c];
    const float cnt = (float)(end - start);
    out_pool[g * FEAT + c] = s / fmaxf(cnt, 1.f);
}

// ---------------------------------------------------------------------------
extern "C" void kernel_launch(void* const* d_in, const int* in_sizes, int n_in,
                              void* d_out, int out_size) {
    const float* x      = (const float*)d_in[0];
    const void*  ei     = d_in[1];
    const void*  bat    = d_in[2];
    const float* W1 = (const float*)d_in[3];
    const float* b1 = (const float*)d_in[4];
    const float* W2 = (const float*)d_in[5];
    const float* b2 = (const float*)d_in[6];
    const float* W3 = (const float*)d_in[7];
    const float* b3 = (const float*)d_in[8];
    const float* W4 = (const float*)d_in[9];
    const float* b4 = (const float*)d_in[10];

    float* out      = (float*)d_out;
    float* out_pool = out;                       // [100,128]
    float* out_h    = out + N_GRAPHS * FEAT;     // [100000,128]

    float *bufA, *bufB;
    cudaGetSymbolAddress((void**)&bufA, g_bufA);
    cudaGetSymbolAddress((void**)&bufB, g_bufB);

    const size_t smem = (size_t)2 * 128 * SA * sizeof(float);  // 132 KB
    cudaFuncSetAttribute(gemm_bias_relu_kernel,
                         cudaFuncAttributeMaxDynamicSharedMemorySize, (int)smem);

    const int n4 = N_NODES * FEAT / 4;
    const int copy_blocks = (n4 + 255) / 256;
    const long long sthreads = (long long)N_EDGES * 32;
    const int scatter_blocks = (int)((sthreads + 255) / 256);
    const int gemm_blocks = (N_NODES + 127) / 128;

    // Detect index dtype (int32 vs int64) once per launch
    detect_kernel<<<1, 1>>>((const int*)ei);

    // Layer 1: agg = x + scatter(x); h1 = relu(relu(agg@W1^T+b1)@W2^T+b2)
    copy_kernel<<<copy_blocks, 256>>>(x, bufA, n4);
    scatter_kernel<<<scatter_blocks, 256>>>(x, bufA, ei);
    gemm_bias_relu_kernel<<<gemm_blocks, 256, smem>>>(bufA, W1, b1, bufB, N_NODES);
    gemm_bias_relu_kernel<<<gemm_blocks, 256, smem>>>(bufB, W2, b2, bufA, N_NODES);

    // Layer 2: agg2 = h1 + scatter(h1); h = relu(relu(agg2@W3^T+b3)@W4^T+b4)
    copy_kernel<<<copy_blocks, 256>>>(bufA, bufB, n4);
    scatter_kernel<<<scatter_blocks, 256>>>(bufA, bufB, ei);
    gemm_bias_relu_kernel<<<gemm_blocks, 256, smem>>>(bufB, W3, b3, bufA, N_NODES);
    gemm_bias_relu_kernel<<<gemm_blocks, 256, smem>>>(bufA, W4, b4, out_h, N_NODES);

    // Global mean pool (batch sorted -> binary search, no atomics)
    pool_kernel<<<N_GRAPHS, FEAT>>>(out_h, bat, out_pool);
}

// round 3
// speedup vs baseline: 1.7608x; 1.7608x over previous
#include <cuda_runtime.h>

#define N_NODES 100000
#define N_EDGES 1600000
#define FEAT 128
#define N_GRAPHS 100
#define SA 132  // smem row stride (floats), %4==0 for 16B-aligned float4 reads

// Scratch (allocation-free rule: __device__ globals)
__device__ float g_bufA[(size_t)N_NODES * FEAT];
__device__ float g_bufB[(size_t)N_NODES * FEAT];
__device__ int   g_deg[N_NODES];
__device__ int   g_rowptr[N_NODES + 1];
__device__ int   g_cursor[N_NODES];
__device__ int   g_csrsrc[N_EDGES];
__device__ int   g_idx64;  // 1 if edge_index/batch are int64, 0 if int32

// ---------------------------------------------------------------------------
// Index dtype detector (int64 little-endian => odd words all zero)
// ---------------------------------------------------------------------------
__global__ void detect_kernel(const int* __restrict__ ei_words) {
    int is64 = 1;
    for (int i = 0; i < 512; i++) {
        int lo = ei_words[2 * i];
        int hi = ei_words[2 * i + 1];
        if (hi != 0 || lo < 0 || lo >= N_NODES) { is64 = 0; break; }
    }
    g_idx64 = is64;
}

__device__ __forceinline__ int load_idx(const void* p, long long i) {
    return g_idx64 ? (int)((const long long*)p)[i] : ((const int*)p)[i];
}

// ---------------------------------------------------------------------------
// CSR build: zero degrees -> histogram(dst) -> exclusive scan -> fill src ids
// ---------------------------------------------------------------------------
__global__ void zero_deg_kernel(int* __restrict__ deg) {
    int i = blockIdx.x * blockDim.x + threadIdx.x;
    if (i < N_NODES) deg[i] = 0;
}

__global__ void hist_kernel(const void* __restrict__ ei, int* __restrict__ deg) {
    int e = blockIdx.x * blockDim.x + threadIdx.x;
    if (e >= N_EDGES) return;
    int d = load_idx(ei, (long long)N_EDGES + e);
    atomicAdd(&deg[d], 1);
}

// single block of 1024 threads: exclusive scan of deg into rowptr & cursor
__global__ void scan_kernel(const int* __restrict__ deg,
                            int* __restrict__ rowptr,
                            int* __restrict__ cursor) {
    __shared__ int part[1024];
    const int t = threadIdx.x;
    const int PER = (N_NODES + 1023) / 1024;  // 98
    const int lo = t * PER;
    const int hi = min(lo + PER, N_NODES);
    int s = 0;
    for (int i = lo; i < hi; i++) s += deg[i];
    part[t] = s;
    __syncthreads();
    // Hillis-Steele inclusive scan
    for (int off = 1; off < 1024; off <<= 1) {
        int tmp = (t >= off) ? part[t - off] : 0;
        __syncthreads();
        part[t] += tmp;
        __syncthreads();
    }
    int running = part[t] - s;  // exclusive prefix for this thread's range
    for (int i = lo; i < hi; i++) {
        rowptr[i] = running;
        cursor[i] = running;
        running += deg[i];
    }
    if (t == 1023) rowptr[N_NODES] = part[1023];
}

__global__ void fill_kernel(const void* __restrict__ ei,
                            int* __restrict__ cursor,
                            int* __restrict__ csrsrc) {
    int e = blockIdx.x * blockDim.x + threadIdx.x;
    if (e >= N_EDGES) return;
    int s = load_idx(ei, e);
    int d = load_idx(ei, (long long)N_EDGES + e);
    int pos = atomicAdd(&cursor[d], 1);
    csrsrc[pos] = s;
}

// ---------------------------------------------------------------------------
// GIN aggregation (gather form): out[n] = x[n] + sum_{e in CSR[n]} x[src[e]]
// One warp per node; lane owns a float4 (4 feature cols). No atomics.
// ---------------------------------------------------------------------------
__global__ void agg_kernel(const float* __restrict__ x,
                           float* __restrict__ out,
                           const int* __restrict__ rowptr,
                           const int* __restrict__ csrsrc) {
    long long t = (long long)blockIdx.x * blockDim.x + threadIdx.x;
    int n = (int)(t >> 5);
    if (n >= N_NODES) return;
    const int lane = (int)(t & 31);

    const int beg = rowptr[n];
    const int end = rowptr[n + 1];

    float4 acc = ((const float4*)(x + (size_t)n * FEAT))[lane];

    for (int base = beg; base < end; base += 32) {
        const int cnt = min(32, end - base);
        int sid = (base + lane < end) ? csrsrc[base + lane] : 0;
#pragma unroll 4
        for (int j = 0; j < cnt; j++) {
            int s = __shfl_sync(0xffffffffu, sid, j);
            float4 v = ((const float4*)(x + (size_t)s * FEAT))[lane];
            acc.x += v.x; acc.y += v.y; acc.z += v.z; acc.w += v.w;
        }
    }
    ((float4*)(out + (size_t)n * FEAT))[lane] = acc;
}

// ---------------------------------------------------------------------------
// C[m][n] = relu( sum_k A[m][k] * W[n][k] + bias[n] )  (unchanged from R2:
// measured at ~88% of fp32 FFMA peak)
// ---------------------------------------------------------------------------
__global__ void gemm_bias_relu_kernel(const float* __restrict__ A,
                                      const float* __restrict__ W,
                                      const float* __restrict__ bias,
                                      float* __restrict__ C, int M) {
    extern __shared__ float sm[];
    float* As = sm;              // As[k*SA + m] = A[row0+m][k]
    float* Bs = sm + 128 * SA;   // Bs[k*SA + n] = W[n][k]

    const int tid = threadIdx.x;
    const int row0 = blockIdx.x * 128;

    {
        const int m = tid & 127;
        const int c0 = tid >> 7;  // 0 or 1
        const int gr = row0 + m;
        const bool in = (gr < M);
        const float4* arow = (const float4*)(A + (size_t)gr * FEAT);
        const float4* wrow = (const float4*)(W + (size_t)m * FEAT);
#pragma unroll
        for (int j = 0; j < 16; j++) {
            const int c = c0 + 2 * j;       // float4 index along k: 0..31
            const int k = 4 * c;
            float4 va = in ? arow[c] : make_float4(0.f, 0.f, 0.f, 0.f);
            As[(k + 0) * SA + m] = va.x;
            As[(k + 1) * SA + m] = va.y;
            As[(k + 2) * SA + m] = va.z;
            As[(k + 3) * SA + m] = va.w;
            float4 vw = wrow[c];
            Bs[(k + 0) * SA + m] = vw.x;
            Bs[(k + 1) * SA + m] = vw.y;
            Bs[(k + 2) * SA + m] = vw.z;
            Bs[(k + 3) * SA + m] = vw.w;
        }
    }
    __syncthreads();

    const int tx = tid & 15;   // n-dim: cols 8*tx .. 8*tx+7
    const int ty = tid >> 4;   // m-dim: rows 8*ty .. 8*ty+7

    float acc[8][8];
#pragma unroll
    for (int i = 0; i < 8; i++)
#pragma unroll
        for (int j = 0; j < 8; j++) acc[i][j] = 0.f;

#pragma unroll 8
    for (int k = 0; k < 128; k++) {
        const float* ap = As + k * SA + 8 * ty;
        const float* bp = Bs + k * SA + 8 * tx;
        float4 a0 = *(const float4*)(ap);
        float4 a1 = *(const float4*)(ap + 4);
        float4 b0 = *(const float4*)(bp);
        float4 b1 = *(const float4*)(bp + 4);
        float a[8] = {a0.x, a0.y, a0.z, a0.w, a1.x, a1.y, a1.z, a1.w};
        float b[8] = {b0.x, b0.y, b0.z, b0.w, b1.x, b1.y, b1.z, b1.w};
#pragma unroll
        for (int i = 0; i < 8; i++)
#pragma unroll
            for (int j = 0; j < 8; j++) acc[i][j] += a[i] * b[j];
    }

    float bv[8];
#pragma unroll
    for (int j = 0; j < 8; j++) bv[j] = bias[8 * tx + j];

#pragma unroll
    for (int i = 0; i < 8; i++) {
        const int m = row0 + 8 * ty + i;
        if (m < M) {
            float4 o0, o1;
            o0.x = fmaxf(acc[i][0] + bv[0], 0.f);
            o0.y = fmaxf(acc[i][1] + bv[1], 0.f);
            o0.z = fmaxf(acc[i][2] + bv[2], 0.f);
            o0.w = fmaxf(acc[i][3] + bv[3], 0.f);
            o1.x = fmaxf(acc[i][4] + bv[4], 0.f);
            o1.y = fmaxf(acc[i][5] + bv[5], 0.f);
            o1.z = fmaxf(acc[i][6] + bv[6], 0.f);
            o1.w = fmaxf(acc[i][7] + bv[7], 0.f);
            float* crow = C + (size_t)m * FEAT + 8 * tx;
            *(float4*)(crow) = o0;
            *(float4*)(crow + 4) = o1;
        }
    }
}

// ---------------------------------------------------------------------------
// Global mean pool per graph (batch is sorted -> binary search ranges).
// ---------------------------------------------------------------------------
__global__ void pool_kernel(const float* __restrict__ h,
                            const void* __restrict__ batch,
                            float* __restrict__ out_pool) {
    const int g = blockIdx.x;
    const int c = threadIdx.x;  // 0..127
    const int is64 = g_idx64;
    const long long* b64 = (const long long*)batch;
    const int* b32 = (const int*)batch;

    int lo = 0, hi = N_NODES;
    while (lo < hi) {
        int mid = (lo + hi) >> 1;
        long long v = is64 ? b64[mid] : (long long)b32[mid];
        if (v < (long long)g) lo = mid + 1; else hi = mid;
    }
    const int start = lo;
    hi = N_NODES;
    while (lo < hi) {
        int mid = (lo + hi) >> 1;
        long long v = is64 ? b64[mid] : (long long)b32[mid];
        if (v < (long long)g + 1) lo = mid + 1; else hi = mid;
    }
    const int end = lo;

    float s = 0.f;
    for (int r = start; r < end; r++) s += h[(size_t)r * FEAT + c];
    const float cnt = (float)(end - start);
    out_pool[g * FEAT + c] = s / fmaxf(cnt, 1.f);
}

// ---------------------------------------------------------------------------
extern "C" void kernel_launch(void* const* d_in, const int* in_sizes, int n_in,
                              void* d_out, int out_size) {
    const float* x   = (const float*)d_in[0];
    const void*  ei  = d_in[1];
    const void*  bat = d_in[2];
    const float* W1 = (const float*)d_in[3];
    const float* b1 = (const float*)d_in[4];
    const float* W2 = (const float*)d_in[5];
    const float* b2 = (const float*)d_in[6];
    const float* W3 = (const float*)d_in[7];
    const float* b3 = (const float*)d_in[8];
    const float* W4 = (const float*)d_in[9];
    const float* b4 = (const float*)d_in[10];

    float* out      = (float*)d_out;
    float* out_pool = out;                       // [100,128]
    float* out_h    = out + N_GRAPHS * FEAT;     // [100000,128]

    float *bufA, *bufB;
    int *deg, *rowptr, *cursor, *csrsrc;
    cudaGetSymbolAddress((void**)&bufA, g_bufA);
    cudaGetSymbolAddress((void**)&bufB, g_bufB);
    cudaGetSymbolAddress((void**)&deg, g_deg);
    cudaGetSymbolAddress((void**)&rowptr, g_rowptr);
    cudaGetSymbolAddress((void**)&cursor, g_cursor);
    cudaGetSymbolAddress((void**)&csrsrc, g_csrsrc);

    const size_t smem = (size_t)2 * 128 * SA * sizeof(float);  // 132 KB
    cudaFuncSetAttribute(gemm_bias_relu_kernel,
                         cudaFuncAttributeMaxDynamicSharedMemorySize, (int)smem);

    const int edge_blocks = (N_EDGES + 255) / 256;
    const int node_blocks = (N_NODES + 255) / 256;
    const long long athreads = (long long)N_NODES * 32;
    const int agg_blocks = (int)((athreads + 255) / 256);
    const int gemm_blocks = (N_NODES + 127) / 128;

    // ---- CSR build (once per launch) ----
    detect_kernel<<<1, 1>>>((const int*)ei);
    zero_deg_kernel<<<node_blocks, 256>>>(deg);
    hist_kernel<<<edge_blocks, 256>>>(ei, deg);
    scan_kernel<<<1, 1024>>>(deg, rowptr, cursor);
    fill_kernel<<<edge_blocks, 256>>>(ei, cursor, csrsrc);

    // ---- Layer 1 ----
    agg_kernel<<<agg_blocks, 256>>>(x, bufA, rowptr, csrsrc);
    gemm_bias_relu_kernel<<<gemm_blocks, 256, smem>>>(bufA, W1, b1, bufB, N_NODES);
    gemm_bias_relu_kernel<<<gemm_blocks, 256, smem>>>(bufB, W2, b2, bufA, N_NODES);

    // ---- Layer 2 ----
    agg_kernel<<<agg_blocks, 256>>>(bufA, bufB, rowptr, csrsrc);
    gemm_bias_relu_kernel<<<gemm_blocks, 256, smem>>>(bufB, W3, b3, bufA, N_NODES);
    gemm_bias_relu_kernel<<<gemm_blocks, 256, smem>>>(bufA, W4, b4, out_h, N_NODES);

    // ---- Global mean pool ----
    pool_kernel<<<N_GRAPHS, FEAT>>>(out_h, bat, out_pool);
}

// round 4
// speedup vs baseline: 2.1276x; 1.2083x over previous
#include <cuda_runtime.h>

#define N_NODES 100000
#define N_EDGES 1600000
#define FEAT 128
#define N_GRAPHS 100
#define SA 132  // smem row stride (floats), %4==0 for 16B-aligned float4 reads

#define SCAN_ITEMS 1024                                  // nodes per scan block
#define SCAN_BLOCKS ((N_NODES + SCAN_ITEMS - 1) / SCAN_ITEMS)  // 98

// Scratch (allocation-free rule: __device__ globals)
__device__ float g_bufA[(size_t)N_NODES * FEAT];
__device__ float g_bufB[(size_t)N_NODES * FEAT];
__device__ int   g_deg[N_NODES];
__device__ int   g_rowptr[N_NODES + 1];
__device__ int   g_cursor[N_NODES];
__device__ int   g_csrsrc[N_EDGES];
__device__ int   g_blocksum[SCAN_BLOCKS];
__device__ int   g_blockoff[SCAN_BLOCKS];
__device__ int   g_idx64;  // 1 if edge_index/batch are int64, 0 if int32

// ---------------------------------------------------------------------------
// Index dtype detector (int64 little-endian => odd words all zero). 1 warp.
// ---------------------------------------------------------------------------
__global__ void detect_kernel(const int* __restrict__ ei_words) {
    const int lane = threadIdx.x;
    int ok = 1;
#pragma unroll
    for (int j = 0; j < 16; j++) {
        int i = j * 32 + lane;
        int lo = ei_words[2 * i];
        int hi = ei_words[2 * i + 1];
        if (hi != 0 || lo < 0 || lo >= N_NODES) ok = 0;
    }
    int all = __all_sync(0xffffffffu, ok);
    if (lane == 0) g_idx64 = all;
}

__device__ __forceinline__ int load_idx(const void* p, long long i) {
    return g_idx64 ? (int)((const long long*)p)[i] : ((const int*)p)[i];
}

// ---------------------------------------------------------------------------
// CSR build: zero degrees -> histogram(dst) -> 3-pass scan -> fill src ids
// ---------------------------------------------------------------------------
__global__ void zero_deg_kernel(int* __restrict__ deg) {
    int i = blockIdx.x * blockDim.x + threadIdx.x;
    if (i < N_NODES) deg[i] = 0;
}

__global__ void hist_kernel(const void* __restrict__ ei, int* __restrict__ deg) {
    int e = blockIdx.x * blockDim.x + threadIdx.x;
    if (e >= N_EDGES) return;
    int d = load_idx(ei, (long long)N_EDGES + e);
    atomicAdd(&deg[d], 1);
}

// Pass A: per-block partial sums (coalesced, 4 items/thread)
__global__ void scanA_kernel(const int* __restrict__ deg, int* __restrict__ blocksum) {
    __shared__ int red[256];
    const int t = threadIdx.x;
    const int base = blockIdx.x * SCAN_ITEMS;
    int s = 0;
#pragma unroll
    for (int j = 0; j < 4; j++) {
        int i = base + t + j * 256;      // coalesced
        if (i < N_NODES) s += deg[i];
    }
    red[t] = s;
    __syncthreads();
    for (int off = 128; off > 0; off >>= 1) {
        if (t < off) red[t] += red[t + off];
        __syncthreads();
    }
    if (t == 0) blocksum[blockIdx.x] = red[0];
}

// Pass B: 1 small block scans SCAN_BLOCKS partial sums (exclusive)
__global__ void scanB_kernel(const int* __restrict__ blocksum,
                             int* __restrict__ blockoff,
                             int* __restrict__ rowptr) {
    __shared__ int v[128];
    const int t = threadIdx.x;  // 128 threads
    v[t] = (t < SCAN_BLOCKS) ? blocksum[t] : 0;
    __syncthreads();
    int mine = v[t];
    for (int off = 1; off < 128; off <<= 1) {
        int tmp = (t >= off) ? v[t - off] : 0;
        __syncthreads();
        v[t] += tmp;
        __syncthreads();
    }
    if (t < SCAN_BLOCKS) blockoff[t] = v[t] - mine;  // exclusive
    if (t == 127) rowptr[N_NODES] = v[127];          // grand total
}

// Pass C: per-block rescan, write rowptr & cursor (exclusive prefixes)
__global__ void scanC_kernel(const int* __restrict__ deg,
                             const int* __restrict__ blockoff,
                             int* __restrict__ rowptr,
                             int* __restrict__ cursor) {
    __shared__ int ts[256];
    const int t = threadIdx.x;
    const int base = blockIdx.x * SCAN_ITEMS + t * 4;  // 4 sequential items/thread
    int d0 = 0, d1 = 0, d2 = 0, d3 = 0;
    if (base + 0 < N_NODES) d0 = deg[base + 0];
    if (base + 1 < N_NODES) d1 = deg[base + 1];
    if (base + 2 < N_NODES) d2 = deg[base + 2];
    if (base + 3 < N_NODES) d3 = deg[base + 3];
    int tot = d0 + d1 + d2 + d3;
    ts[t] = tot;
    __syncthreads();
    int inc = tot;
    for (int off = 1; off < 256; off <<= 1) {
        int tmp = (t >= off) ? ts[t - off] : 0;
        __syncthreads();
        ts[t] += tmp;
        __syncthreads();
    }
    inc = ts[t];  // inclusive
    int run = blockoff[blockIdx.x] + inc - tot;  // exclusive start for this thread
    if (base + 0 < N_NODES) { rowptr[base + 0] = run; cursor[base + 0] = run; run += d0; }
    if (base + 1 < N_NODES) { rowptr[base + 1] = run; cursor[base + 1] = run; run += d1; }
    if (base + 2 < N_NODES) { rowptr[base + 2] = run; cursor[base + 2] = run; run += d2; }
    if (base + 3 < N_NODES) { rowptr[base + 3] = run; cursor[base + 3] = run; run += d3; }
}

__global__ void fill_kernel(const void* __restrict__ ei,
                            int* __restrict__ cursor,
                            int* __restrict__ csrsrc) {
    int e = blockIdx.x * blockDim.x + threadIdx.x;
    if (e >= N_EDGES) return;
    int s = load_idx(ei, e);
    int d = load_idx(ei, (long long)N_EDGES + e);
    int pos = atomicAdd(&cursor[d], 1);
    csrsrc[pos] = s;
}

// ---------------------------------------------------------------------------
// GIN aggregation (gather form): out[n] = x[n] + sum_{e in CSR[n]} x[src[e]]
// One warp per node; lane owns a float4 (4 feature cols). No atomics.
// ---------------------------------------------------------------------------
__global__ void agg_kernel(const float* __restrict__ x,
                           float* __restrict__ out,
                           const int* __restrict__ rowptr,
                           const int* __restrict__ csrsrc) {
    long long t = (long long)blockIdx.x * blockDim.x + threadIdx.x;
    int n = (int)(t >> 5);
    if (n >= N_NODES) return;
    const int lane = (int)(t & 31);

    const int beg = rowptr[n];
    const int end = rowptr[n + 1];

    float4 acc = ((const float4*)(x + (size_t)n * FEAT))[lane];

    for (int base = beg; base < end; base += 32) {
        const int cnt = min(32, end - base);
        int sid = (base + lane < end) ? csrsrc[base + lane] : 0;
#pragma unroll 4
        for (int j = 0; j < cnt; j++) {
            int s = __shfl_sync(0xffffffffu, sid, j);
            float4 v = ((const float4*)(x + (size_t)s * FEAT))[lane];
            acc.x += v.x; acc.y += v.y; acc.z += v.z; acc.w += v.w;
        }
    }
    ((float4*)(out + (size_t)n * FEAT))[lane] = acc;
}

// ---------------------------------------------------------------------------
// C[m][n] = relu( sum_k A[m][k] * W[n][k] + bias[n] )  (measured ~83% of fp32
// FFMA ceiling — unchanged)
// ---------------------------------------------------------------------------
__global__ void gemm_bias_relu_kernel(const float* __restrict__ A,
                                      const float* __restrict__ W,
                                      const float* __restrict__ bias,
                                      float* __restrict__ C, int M) {
    extern __shared__ float sm[];
    float* As = sm;              // As[k*SA + m] = A[row0+m][k]
    float* Bs = sm + 128 * SA;   // Bs[k*SA + n] = W[n][k]

    const int tid = threadIdx.x;
    const int row0 = blockIdx.x * 128;

    {
        const int m = tid & 127;
        const int c0 = tid >> 7;  // 0 or 1
        const int gr = row0 + m;
        const bool in = (gr < M);
        const float4* arow = (const float4*)(A + (size_t)gr * FEAT);
        const float4* wrow = (const float4*)(W + (size_t)m * FEAT);
#pragma unroll
        for (int j = 0; j < 16; j++) {
            const int c = c0 + 2 * j;       // float4 index along k: 0..31
            const int k = 4 * c;
            float4 va = in ? arow[c] : make_float4(0.f, 0.f, 0.f, 0.f);
            As[(k + 0) * SA + m] = va.x;
            As[(k + 1) * SA + m] = va.y;
            As[(k + 2) * SA + m] = va.z;
            As[(k + 3) * SA + m] = va.w;
            float4 vw = wrow[c];
            Bs[(k + 0) * SA + m] = vw.x;
            Bs[(k + 1) * SA + m] = vw.y;
            Bs[(k + 2) * SA + m] = vw.z;
            Bs[(k + 3) * SA + m] = vw.w;
        }
    }
    __syncthreads();

    const int tx = tid & 15;   // n-dim: cols 8*tx .. 8*tx+7
    const int ty = tid >> 4;   // m-dim: rows 8*ty .. 8*ty+7

    float acc[8][8];
#pragma unroll
    for (int i = 0; i < 8; i++)
#pragma unroll
        for (int j = 0; j < 8; j++) acc[i][j] = 0.f;

#pragma unroll 8
    for (int k = 0; k < 128; k++) {
        const float* ap = As + k * SA + 8 * ty;
        const float* bp = Bs + k * SA + 8 * tx;
        float4 a0 = *(const float4*)(ap);
        float4 a1 = *(const float4*)(ap + 4);
        float4 b0 = *(const float4*)(bp);
        float4 b1 = *(const float4*)(bp + 4);
        float a[8] = {a0.x, a0.y, a0.z, a0.w, a1.x, a1.y, a1.z, a1.w};
        float b[8] = {b0.x, b0.y, b0.z, b0.w, b1.x, b1.y, b1.z, b1.w};
#pragma unroll
        for (int i = 0; i < 8; i++)
#pragma unroll
            for (int j = 0; j < 8; j++) acc[i][j] += a[i] * b[j];
    }

    float bv[8];
#pragma unroll
    for (int j = 0; j < 8; j++) bv[j] = bias[8 * tx + j];

#pragma unroll
    for (int i = 0; i < 8; i++) {
        const int m = row0 + 8 * ty + i;
        if (m < M) {
            float4 o0, o1;
            o0.x = fmaxf(acc[i][0] + bv[0], 0.f);
            o0.y = fmaxf(acc[i][1] + bv[1], 0.f);
            o0.z = fmaxf(acc[i][2] + bv[2], 0.f);
            o0.w = fmaxf(acc[i][3] + bv[3], 0.f);
            o1.x = fmaxf(acc[i][4] + bv[4], 0.f);
            o1.y = fmaxf(acc[i][5] + bv[5], 0.f);
            o1.z = fmaxf(acc[i][6] + bv[6], 0.f);
            o1.w = fmaxf(acc[i][7] + bv[7], 0.f);
            float* crow = C + (size_t)m * FEAT + 8 * tx;
            *(float4*)(crow) = o0;
            *(float4*)(crow + 4) = o1;
        }
    }
}

// ---------------------------------------------------------------------------
// Global mean pool per graph (batch is sorted -> binary search ranges).
// ---------------------------------------------------------------------------
__global__ void pool_kernel(const float* __restrict__ h,
                            const void* __restrict__ batch,
                            float* __restrict__ out_pool) {
    const int g = blockIdx.x;
    const int c = threadIdx.x;  // 0..127
    const int is64 = g_idx64;
    const long long* b64 = (const long long*)batch;
    const int* b32 = (const int*)batch;

    int lo = 0, hi = N_NODES;
    while (lo < hi) {
        int mid = (lo + hi) >> 1;
        long long v = is64 ? b64[mid] : (long long)b32[mid];
        if (v < (long long)g) lo = mid + 1; else hi = mid;
    }
    const int start = lo;
    hi = N_NODES;
    while (lo < hi) {
        int mid = (lo + hi) >> 1;
        long long v = is64 ? b64[mid] : (long long)b32[mid];
        if (v < (long long)g + 1) lo = mid + 1; else hi = mid;
    }
    const int end = lo;

    float s = 0.f;
    for (int r = start; r < end; r++) s += h[(size_t)r * FEAT + c];
    const float cnt = (float)(end - start);
    out_pool[g * FEAT + c] = s / fmaxf(cnt, 1.f);
}

// ---------------------------------------------------------------------------
extern "C" void kernel_launch(void* const* d_in, const int* in_sizes, int n_in,
                              void* d_out, int out_size) {
    const float* x   = (const float*)d_in[0];
    const void*  ei  = d_in[1];
    const void*  bat = d_in[2];
    const float* W1 = (const float*)d_in[3];
    const float* b1 = (const float*)d_in[4];
    const float* W2 = (const float*)d_in[5];
    const float* b2 = (const float*)d_in[6];
    const float* W3 = (const float*)d_in[7];
    const float* b3 = (const float*)d_in[8];
    const float* W4 = (const float*)d_in[9];
    const float* b4 = (const float*)d_in[10];

    float* out      = (float*)d_out;
    float* out_pool = out;                       // [100,128]
    float* out_h    = out + N_GRAPHS * FEAT;     // [100000,128]

    float *bufA, *bufB;
    int *deg, *rowptr, *cursor, *csrsrc, *blocksum, *blockoff;
    cudaGetSymbolAddress((void**)&bufA, g_bufA);
    cudaGetSymbolAddress((void**)&bufB, g_bufB);
    cudaGetSymbolAddress((void**)&deg, g_deg);
    cudaGetSymbolAddress((void**)&rowptr, g_rowptr);
    cudaGetSymbolAddress((void**)&cursor, g_cursor);
    cudaGetSymbolAddress((void**)&csrsrc, g_csrsrc);
    cudaGetSymbolAddress((void**)&blocksum, g_blocksum);
    cudaGetSymbolAddress((void**)&blockoff, g_blockoff);

    const size_t smem = (size_t)2 * 128 * SA * sizeof(float);  // 132 KB
    cudaFuncSetAttribute(gemm_bias_relu_kernel,
                         cudaFuncAttributeMaxDynamicSharedMemorySize, (int)smem);

    const int edge_blocks = (N_EDGES + 255) / 256;
    const int node_blocks = (N_NODES + 255) / 256;
    const long long athreads = (long long)N_NODES * 32;
    const int agg_blocks = (int)((athreads + 255) / 256);
    const int gemm_blocks = (N_NODES + 127) / 128;

    // ---- CSR build (once per launch) ----
    detect_kernel<<<1, 32>>>((const int*)ei);
    zero_deg_kernel<<<node_blocks, 256>>>(deg);
    hist_kernel<<<edge_blocks, 256>>>(ei, deg);
    scanA_kernel<<<SCAN_BLOCKS, 256>>>(deg, blocksum);
    scanB_kernel<<<1, 128>>>(blocksum, blockoff, rowptr);
    scanC_kernel<<<SCAN_BLOCKS, 256>>>(deg, blockoff, rowptr, cursor);
    fill_kernel<<<edge_blocks, 256>>>(ei, cursor, csrsrc);

    // ---- Layer 1 ----
    agg_kernel<<<agg_blocks, 256>>>(x, bufA, rowptr, csrsrc);
    gemm_bias_relu_kernel<<<gemm_blocks, 256, smem>>>(bufA, W1, b1, bufB, N_NODES);
    gemm_bias_relu_kernel<<<gemm_blocks, 256, smem>>>(bufB, W2, b2, bufA, N_NODES);

    // ---- Layer 2 ----
    agg_kernel<<<agg_blocks, 256>>>(bufA, bufB, rowptr, csrsrc);
    gemm_bias_relu_kernel<<<gemm_blocks, 256, smem>>>(bufB, W3, b3, bufA, N_NODES);
    gemm_bias_relu_kernel<<<gemm_blocks, 256, smem>>>(bufA, W4, b4, out_h, N_NODES);

    // ---- Global mean pool ----
    pool_kernel<<<N_GRAPHS, FEAT>>>(out_h, bat, out_pool);
}

// round 6
// speedup vs baseline: 2.8705x; 1.3492x over previous
#include <cuda_runtime.h>
#include <cuda_bf16.h>
#include <cstdint>

#define N_NODES 100000
#define N_EDGES 1600000
#define FEAT 128
#define N_GRAPHS 100

#define SCAN_ITEMS 1024
#define SCAN_BLOCKS ((N_NODES + SCAN_ITEMS - 1) / SCAN_ITEMS)  // 98

// Scratch (allocation-free rule: __device__ globals)
__device__ float g_bufA[(size_t)N_NODES * FEAT];
__device__ float g_bufB[(size_t)N_NODES * FEAT];
__device__ int   g_deg[N_NODES];
__device__ int   g_rowptr[N_NODES + 1];
__device__ int   g_cursor[N_NODES];
__device__ int   g_csrsrc[N_EDGES];
__device__ int   g_blocksum[SCAN_BLOCKS];
__device__ int   g_blockoff[SCAN_BLOCKS];
__device__ int   g_idx64;

// ===========================================================================
// Helpers
// ===========================================================================
__device__ __forceinline__ uint32_t smem_u32(const void* p) {
    uint32_t a;
    asm("{ .reg .u64 t; cvta.to.shared.u64 t, %1; cvt.u32.u64 %0, t; }" : "=r"(a) : "l"(p));
    return a;
}
__device__ __forceinline__ uint32_t pack_bf16(float a, float b) {
    uint32_t r;
    asm("cvt.rn.bf16x2.f32 %0, %1, %2;" : "=r"(r) : "f"(b), "f"(a));
    return r;
}
__device__ __forceinline__ void ldsm_x4(uint32_t* r, uint32_t addr) {
    asm volatile("ldmatrix.sync.aligned.m8n8.x4.shared.b16 {%0,%1,%2,%3}, [%4];"
        : "=r"(r[0]), "=r"(r[1]), "=r"(r[2]), "=r"(r[3]) : "r"(addr));
}
__device__ __forceinline__ void mma_bf16(float* c, const uint32_t* a, const uint32_t* b) {
    asm volatile("mma.sync.aligned.m16n8k16.row.col.f32.bf16.bf16.f32 "
        "{%0,%1,%2,%3}, {%4,%5,%6,%7}, {%8,%9}, {%0,%1,%2,%3};"
        : "+f"(c[0]), "+f"(c[1]), "+f"(c[2]), "+f"(c[3])
        : "r"(a[0]), "r"(a[1]), "r"(a[2]), "r"(a[3]), "r"(b[0]), "r"(b[1]));
}

// ===========================================================================
// Index dtype detector (int64 little-endian => odd words zero). 1 warp.
// ===========================================================================
__global__ void detect_kernel(const int* __restrict__ ei_words) {
    const int lane = threadIdx.x;
    int ok = 1;
#pragma unroll
    for (int j = 0; j < 16; j++) {
        int i = j * 32 + lane;
        int lo = ei_words[2 * i];
        int hi = ei_words[2 * i + 1];
        if (hi != 0 || lo < 0 || lo >= N_NODES) ok = 0;
    }
    int all = __all_sync(0xffffffffu, ok);
    if (lane == 0) g_idx64 = all;
}
__device__ __forceinline__ int load_idx(const void* p, long long i) {
    return g_idx64 ? (int)((const long long*)p)[i] : ((const int*)p)[i];
}

// ===========================================================================
// CSR build
// ===========================================================================
__global__ void zero_deg_kernel(int* __restrict__ deg) {
    int i = blockIdx.x * blockDim.x + threadIdx.x;
    if (i < N_NODES) deg[i] = 0;
}
__global__ void hist_kernel(const void* __restrict__ ei, int* __restrict__ deg) {
    int e = blockIdx.x * blockDim.x + threadIdx.x;
    if (e >= N_EDGES) return;
    atomicAdd(&deg[load_idx(ei, (long long)N_EDGES + e)], 1);
}
__global__ void scanA_kernel(const int* __restrict__ deg, int* __restrict__ blocksum) {
    __shared__ int red[256];
    const int t = threadIdx.x;
    const int base = blockIdx.x * SCAN_ITEMS;
    int s = 0;
#pragma unroll
    for (int j = 0; j < 4; j++) {
        int i = base + t + j * 256;
        if (i < N_NODES) s += deg[i];
    }
    red[t] = s;
    __syncthreads();
    for (int off = 128; off > 0; off >>= 1) {
        if (t < off) red[t] += red[t + off];
        __syncthreads();
    }
    if (t == 0) blocksum[blockIdx.x] = red[0];
}
__global__ void scanB_kernel(const int* __restrict__ blocksum,
                             int* __restrict__ blockoff, int* __restrict__ rowptr) {
    __shared__ int v[128];
    const int t = threadIdx.x;
    v[t] = (t < SCAN_BLOCKS) ? blocksum[t] : 0;
    __syncthreads();
    int mine = v[t];
    for (int off = 1; off < 128; off <<= 1) {
        int tmp = (t >= off) ? v[t - off] : 0;
        __syncthreads();
        v[t] += tmp;
        __syncthreads();
    }
    if (t < SCAN_BLOCKS) blockoff[t] = v[t] - mine;
    if (t == 127) rowptr[N_NODES] = v[127];
}
__global__ void scanC_kernel(const int* __restrict__ deg, const int* __restrict__ blockoff,
                             int* __restrict__ rowptr, int* __restrict__ cursor) {
    __shared__ int ts[256];
    const int t = threadIdx.x;
    const int base = blockIdx.x * SCAN_ITEMS + t * 4;
    int d0 = 0, d1 = 0, d2 = 0, d3 = 0;
    if (base + 0 < N_NODES) d0 = deg[base + 0];
    if (base + 1 < N_NODES) d1 = deg[base + 1];
    if (base + 2 < N_NODES) d2 = deg[base + 2];
    if (base + 3 < N_NODES) d3 = deg[base + 3];
    int tot = d0 + d1 + d2 + d3;
    ts[t] = tot;
    __syncthreads();
    for (int off = 1; off < 256; off <<= 1) {
        int tmp = (t >= off) ? ts[t - off] : 0;
        __syncthreads();
        ts[t] += tmp;
        __syncthreads();
    }
    int run = blockoff[blockIdx.x] + ts[t] - tot;
    if (base + 0 < N_NODES) { rowptr[base + 0] = run; cursor[base + 0] = run; run += d0; }
    if (base + 1 < N_NODES) { rowptr[base + 1] = run; cursor[base + 1] = run; run += d1; }
    if (base + 2 < N_NODES) { rowptr[base + 2] = run; cursor[base + 2] = run; run += d2; }
    if (base + 3 < N_NODES) { rowptr[base + 3] = run; cursor[base + 3] = run; run += d3; }
}
__global__ void fill_kernel(const void* __restrict__ ei,
                            int* __restrict__ cursor, int* __restrict__ csrsrc) {
    int e = blockIdx.x * blockDim.x + threadIdx.x;
    if (e >= N_EDGES) return;
    int s = load_idx(ei, e);
    int d = load_idx(ei, (long long)N_EDGES + e);
    csrsrc[atomicAdd(&cursor[d], 1)] = s;
}

// ===========================================================================
// GIN aggregation (gather): out[n] = x[n] + sum_{e in CSR[n]} x[src[e]]
// ===========================================================================
__global__ void agg_kernel(const float* __restrict__ x, float* __restrict__ out,
                           const int* __restrict__ rowptr, const int* __restrict__ csrsrc) {
    long long t = (long long)blockIdx.x * blockDim.x + threadIdx.x;
    int n = (int)(t >> 5);
    if (n >= N_NODES) return;
    const int lane = (int)(t & 31);
    const int beg = rowptr[n];
    const int end = rowptr[n + 1];
    float4 acc = ((const float4*)(x + (size_t)n * FEAT))[lane];
    for (int base = beg; base < end; base += 32) {
        const int cnt = min(32, end - base);
        int sid = (base + lane < end) ? csrsrc[base + lane] : 0;
#pragma unroll 4
        for (int j = 0; j < cnt; j++) {
            int s = __shfl_sync(0xffffffffu, sid, j);
            float4 v = ((const float4*)(x + (size_t)s * FEAT))[lane];
            acc.x += v.x; acc.y += v.y; acc.z += v.z; acc.w += v.w;
        }
    }
    ((float4*)(out + (size_t)n * FEAT))[lane] = acc;
}

// ===========================================================================
// bf16-split tensor-core GEMM via mma.sync (HMMA):
//   C[m][n] = relu( sum_k A[m][k]*W[n][k] + bias[n] )
// A,W fp32 -> (hi,lo) bf16; acc += Ahi*Whi + Ahi*Wlo + Alo*Whi (fp32).
// Block: 128(M) x 128(N) x 128(K) one-shot. 8 warps: 4(M) x 2(N).
// Warp tile 32x64 = 2 m16-blocks x 8 n-octets, m16n8k16 fragments.
// W[n][k] row-major IS col-major B => ldmatrix non-trans for both A and B.
// ===========================================================================
#define SAB 136                         // bf16 elements per smem row (272B: conflict-free)
#define TILE_B (128 * SAB * 2)          // 34816 bytes per tile
#define SMB_BIAS 0
#define SMB_AHI  512
#define SMB_ALO  (512 + TILE_B)
#define SMB_WHI  (512 + 2 * TILE_B)
#define SMB_WLO  (512 + 3 * TILE_B)
#define SMB_TOTAL (512 + 4 * TILE_B)    // 139776 bytes

__global__ void __launch_bounds__(256)
gemm_mma_kernel(const float* __restrict__ A, const float* __restrict__ W,
                const float* __restrict__ bias, float* __restrict__ C, int M) {
    extern __shared__ char smem[];
    const uint32_t sb = smem_u32(smem);
    const int tid = threadIdx.x;
    const int lane = tid & 31;
    const int wid = tid >> 5;
    const int row0 = blockIdx.x * 128;

    if (tid < 128) ((float*)(smem + SMB_BIAS))[tid] = bias[tid];

    // ---- convert fp32 -> (hi,lo) bf16 into padded smem ----
    {
        const int r = tid >> 1;          // row 0..127
        const int half = tid & 1;        // k 0..63 / 64..127
        const int gr = row0 + r;
        const bool in = (gr < M);
        const float4* arow = (const float4*)(A + (size_t)gr * FEAT);
        const float4* wrow = (const float4*)(W + (size_t)r * FEAT);
#pragma unroll
        for (int j = 0; j < 16; j++) {
            const int col = half * 64 + j * 4;
            const uint32_t off = (uint32_t)(r * SAB + col) * 2;
            float4 va = in ? arow[half * 16 + j] : make_float4(0.f, 0.f, 0.f, 0.f);
            float h0 = __bfloat162float(__float2bfloat16_rn(va.x));
            float h1 = __bfloat162float(__float2bfloat16_rn(va.y));
            float h2 = __bfloat162float(__float2bfloat16_rn(va.z));
            float h3 = __bfloat162float(__float2bfloat16_rn(va.w));
            *(uint2*)(smem + SMB_AHI + off) = make_uint2(pack_bf16(h0, h1), pack_bf16(h2, h3));
            *(uint2*)(smem + SMB_ALO + off) =
                make_uint2(pack_bf16(va.x - h0, va.y - h1), pack_bf16(va.z - h2, va.w - h3));
            float4 vw = wrow[half * 16 + j];
            float g0 = __bfloat162float(__float2bfloat16_rn(vw.x));
            float g1 = __bfloat162float(__float2bfloat16_rn(vw.y));
            float g2 = __bfloat162float(__float2bfloat16_rn(vw.z));
            float g3 = __bfloat162float(__float2bfloat16_rn(vw.w));
            *(uint2*)(smem + SMB_WHI + off) = make_uint2(pack_bf16(g0, g1), pack_bf16(g2, g3));
            *(uint2*)(smem + SMB_WLO + off) =
                make_uint2(pack_bf16(vw.x - g0, vw.y - g1), pack_bf16(vw.z - g2, vw.w - g3));
        }
    }
    __syncthreads();

    // ---- warp tiling: 4 warps along M (32 rows each), 2 along N (64 cols) ----
    const int m0 = (wid & 3) * 32;
    const int n0 = (wid >> 2) * 64;
    const int g = lane >> 3, r = lane & 7;

    // ldmatrix lane addresses (advance +32B per k-step)
    // A tiles (per m-block): row = m0+mb*16+(g&1)*8+r, col = (g>>1)*8
    uint32_t aH[2], aL[2];
#pragma unroll
    for (int mb = 0; mb < 2; mb++) {
        const uint32_t o = (uint32_t)((m0 + mb * 16 + (g & 1) * 8 + r) * SAB + (g >> 1) * 8) * 2;
        aH[mb] = sb + SMB_AHI + o;
        aL[mb] = sb + SMB_ALO + o;
    }
    // B tiles (per octet pair p): n = n0+p*16+(g>>1)*8+r, col = (g&1)*8
    uint32_t bH[4], bL[4];
#pragma unroll
    for (int p = 0; p < 4; p++) {
        const uint32_t o = (uint32_t)((n0 + p * 16 + (g >> 1) * 8 + r) * SAB + (g & 1) * 8) * 2;
        bH[p] = sb + SMB_WHI + o;
        bL[p] = sb + SMB_WLO + o;
    }

    float acc[2][8][4];
#pragma unroll
    for (int mb = 0; mb < 2; mb++)
#pragma unroll
        for (int o = 0; o < 8; o++)
#pragma unroll
            for (int q = 0; q < 4; q++) acc[mb][o][q] = 0.f;

#pragma unroll
    for (int kk = 0; kk < 8; kk++) {
        uint32_t ah[2][4], al[2][4], bb[4][4];
        ldsm_x4(ah[0], aH[0]); ldsm_x4(ah[1], aH[1]);
        ldsm_x4(al[0], aL[0]); ldsm_x4(al[1], aL[1]);
        ldsm_x4(bb[0], bH[0]); ldsm_x4(bb[1], bH[1]);
        ldsm_x4(bb[2], bH[2]); ldsm_x4(bb[3], bH[3]);
#pragma unroll
        for (int mb = 0; mb < 2; mb++)
#pragma unroll
            for (int o = 0; o < 8; o++) {
                const uint32_t* b = &bb[o >> 1][(o & 1) * 2];
                mma_bf16(acc[mb][o], ah[mb], b);   // hi*hi
                mma_bf16(acc[mb][o], al[mb], b);   // lo*hi
            }
        ldsm_x4(bb[0], bL[0]); ldsm_x4(bb[1], bL[1]);
        ldsm_x4(bb[2], bL[2]); ldsm_x4(bb[3], bL[3]);
#pragma unroll
        for (int mb = 0; mb < 2; mb++)
#pragma unroll
            for (int o = 0; o < 8; o++)
                mma_bf16(acc[mb][o], ah[mb], &bb[o >> 1][(o & 1) * 2]);  // hi*lo
#pragma unroll
        for (int i = 0; i < 2; i++) { aH[i] += 32; aL[i] += 32; }
#pragma unroll
        for (int i = 0; i < 4; i++) { bH[i] += 32; bL[i] += 32; }
    }

    // ---- epilogue: bias + relu, float2 stores ----
    const float* bs = (const float*)(smem + SMB_BIAS);
#pragma unroll
    for (int mb = 0; mb < 2; mb++) {
        const int rbase = row0 + m0 + mb * 16 + (lane >> 2);
#pragma unroll
        for (int o = 0; o < 8; o++) {
            const int col = n0 + o * 8 + (lane & 3) * 2;
            const float b0 = bs[col], b1 = bs[col + 1];
            if (rbase < M) {
                float2 v = make_float2(fmaxf(acc[mb][o][0] + b0, 0.f),
                                       fmaxf(acc[mb][o][1] + b1, 0.f));
                *(float2*)(C + (size_t)rbase * FEAT + col) = v;
            }
            if (rbase + 8 < M) {
                float2 v = make_float2(fmaxf(acc[mb][o][2] + b0, 0.f),
                                       fmaxf(acc[mb][o][3] + b1, 0.f));
                *(float2*)(C + (size_t)(rbase + 8) * FEAT + col) = v;
            }
        }
    }
}

// ===========================================================================
// Global mean pool per graph (batch sorted -> binary search)
// ===========================================================================
__global__ void pool_kernel(const float* __restrict__ h, const void* __restrict__ batch,
                            float* __restrict__ out_pool) {
    const int g = blockIdx.x;
    const int c = threadIdx.x;
    const int is64 = g_idx64;
    const long long* b64 = (const long long*)batch;
    const int* b32 = (const int*)batch;

    int lo = 0, hi = N_NODES;
    while (lo < hi) {
        int mid = (lo + hi) >> 1;
        long long v = is64 ? b64[mid] : (long long)b32[mid];
        if (v < (long long)g) lo = mid + 1; else hi = mid;
    }
    const int start = lo;
    hi = N_NODES;
    while (lo < hi) {
        int mid = (lo + hi) >> 1;
        long long v = is64 ? b64[mid] : (long long)b32[mid];
        if (v < (long long)g + 1) lo = mid + 1; else hi = mid;
    }
    const int end = lo;

    float s = 0.f;
    for (int r = start; r < end; r++) s += h[(size_t)r * FEAT + c];
    out_pool[g * FEAT + c] = s / fmaxf((float)(end - start), 1.f);
}

// ===========================================================================
extern "C" void kernel_launch(void* const* d_in, const int* in_sizes, int n_in,
                              void* d_out, int out_size) {
    const float* x   = (const float*)d_in[0];
    const void*  ei  = d_in[1];
    const void*  bat = d_in[2];
    const float* W1 = (const float*)d_in[3];
    const float* b1 = (const float*)d_in[4];
    const float* W2 = (const float*)d_in[5];
    const float* b2 = (const float*)d_in[6];
    const float* W3 = (const float*)d_in[7];
    const float* b3 = (const float*)d_in[8];
    const float* W4 = (const float*)d_in[9];
    const float* b4 = (const float*)d_in[10];

    float* out      = (float*)d_out;
    float* out_pool = out;
    float* out_h    = out + N_GRAPHS * FEAT;

    float *bufA, *bufB;
    int *deg, *rowptr, *cursor, *csrsrc, *blocksum, *blockoff;
    cudaGetSymbolAddress((void**)&bufA, g_bufA);
    cudaGetSymbolAddress((void**)&bufB, g_bufB);
    cudaGetSymbolAddress((void**)&deg, g_deg);
    cudaGetSymbolAddress((void**)&rowptr, g_rowptr);
    cudaGetSymbolAddress((void**)&cursor, g_cursor);
    cudaGetSymbolAddress((void**)&csrsrc, g_csrsrc);
    cudaGetSymbolAddress((void**)&blocksum, g_blocksum);
    cudaGetSymbolAddress((void**)&blockoff, g_blockoff);

    cudaFuncSetAttribute(gemm_mma_kernel,
                         cudaFuncAttributeMaxDynamicSharedMemorySize, SMB_TOTAL);

    const int edge_blocks = (N_EDGES + 255) / 256;
    const int node_blocks = (N_NODES + 255) / 256;
    const long long athreads = (long long)N_NODES * 32;
    const int agg_blocks = (int)((athreads + 255) / 256);
    const int gemm_blocks = (N_NODES + 127) / 128;

    // ---- CSR build ----
    detect_kernel<<<1, 32>>>((const int*)ei);
    zero_deg_kernel<<<node_blocks, 256>>>(deg);
    hist_kernel<<<edge_blocks, 256>>>(ei, deg);
    scanA_kernel<<<SCAN_BLOCKS, 256>>>(deg, blocksum);
    scanB_kernel<<<1, 128>>>(blocksum, blockoff, rowptr);
    scanC_kernel<<<SCAN_BLOCKS, 256>>>(deg, blockoff, rowptr, cursor);
    fill_kernel<<<edge_blocks, 256>>>(ei, cursor, csrsrc);

    // ---- Layer 1 ----
    agg_kernel<<<agg_blocks, 256>>>(x, bufA, rowptr, csrsrc);
    gemm_mma_kernel<<<gemm_blocks, 256, SMB_TOTAL>>>(bufA, W1, b1, bufB, N_NODES);
    gemm_mma_kernel<<<gemm_blocks, 256, SMB_TOTAL>>>(bufB, W2, b2, bufA, N_NODES);

    // ---- Layer 2 ----
    agg_kernel<<<agg_blocks, 256>>>(bufA, bufB, rowptr, csrsrc);
    gemm_mma_kernel<<<gemm_blocks, 256, SMB_TOTAL>>>(bufB, W3, b3, bufA, N_NODES);
    gemm_mma_kernel<<<gemm_blocks, 256, SMB_TOTAL>>>(bufA, W4, b4, out_h, N_NODES);

    // ---- Global mean pool ----
    pool_kernel<<<N_GRAPHS, FEAT>>>(out_h, bat, out_pool);
}

// round 7
// speedup vs baseline: 3.5850x; 1.2489x over previous
#include <cuda_runtime.h>
#include <cuda_bf16.h>
#include <cstdint>

#define N_NODES 100000
#define N_EDGES 1600000
#define FEAT 128
#define N_GRAPHS 100

#define SCAN_ITEMS 1024
#define SCAN_BLOCKS ((N_NODES + SCAN_ITEMS - 1) / SCAN_ITEMS)  // 98

// Scratch (allocation-free rule: __device__ globals)
__device__ float g_bufA[(size_t)N_NODES * FEAT];
__device__ float g_bufB[(size_t)N_NODES * FEAT];
__device__ int   g_deg[N_NODES];
__device__ int   g_rowptr[N_NODES + 1];
__device__ int   g_cursor[N_NODES];
__device__ int   g_csrsrc[N_EDGES];
__device__ int   g_blocksum[SCAN_BLOCKS];
__device__ int   g_blockoff[SCAN_BLOCKS];
__device__ int   g_idx64;

// ===========================================================================
// Helpers
// ===========================================================================
__device__ __forceinline__ uint32_t smem_u32(const void* p) {
    uint32_t a;
    asm("{ .reg .u64 t; cvta.to.shared.u64 t, %1; cvt.u32.u64 %0, t; }" : "=r"(a) : "l"(p));
    return a;
}
__device__ __forceinline__ uint32_t pack_bf16(float a, float b) {
    uint32_t r;
    asm("cvt.rn.bf16x2.f32 %0, %1, %2;" : "=r"(r) : "f"(b), "f"(a));
    return r;
}
__device__ __forceinline__ void ldsm_x4(uint32_t* r, uint32_t addr) {
    asm volatile("ldmatrix.sync.aligned.m8n8.x4.shared.b16 {%0,%1,%2,%3}, [%4];"
        : "=r"(r[0]), "=r"(r[1]), "=r"(r[2]), "=r"(r[3]) : "r"(addr));
}
__device__ __forceinline__ void mma_bf16(float* c, const uint32_t* a, const uint32_t* b) {
    asm volatile("mma.sync.aligned.m16n8k16.row.col.f32.bf16.bf16.f32 "
        "{%0,%1,%2,%3}, {%4,%5,%6,%7}, {%8,%9}, {%0,%1,%2,%3};"
        : "+f"(c[0]), "+f"(c[1]), "+f"(c[2]), "+f"(c[3])
        : "r"(a[0]), "r"(a[1]), "r"(a[2]), "r"(a[3]), "r"(b[0]), "r"(b[1]));
}
__device__ __forceinline__ void cp16(uint32_t saddr, const void* gptr) {
    asm volatile("cp.async.cg.shared.global [%0], [%1], 16;" :: "r"(saddr), "l"(gptr));
}
#define CP_COMMIT() asm volatile("cp.async.commit_group;" ::: "memory")
#define CP_WAIT0()  asm volatile("cp.async.wait_group 0;" ::: "memory")

// ===========================================================================
// Index dtype detector (int64 little-endian => odd words zero). 1 warp.
// ===========================================================================
__global__ void detect_kernel(const int* __restrict__ ei_words) {
    const int lane = threadIdx.x;
    int ok = 1;
#pragma unroll
    for (int j = 0; j < 16; j++) {
        int i = j * 32 + lane;
        int lo = ei_words[2 * i];
        int hi = ei_words[2 * i + 1];
        if (hi != 0 || lo < 0 || lo >= N_NODES) ok = 0;
    }
    int all = __all_sync(0xffffffffu, ok);
    if (lane == 0) g_idx64 = all;
}
__device__ __forceinline__ int load_idx(const void* p, long long i) {
    return g_idx64 ? (int)((const long long*)p)[i] : ((const int*)p)[i];
}

// ===========================================================================
// CSR build
// ===========================================================================
__global__ void zero_deg_kernel(int* __restrict__ deg) {
    int i = blockIdx.x * blockDim.x + threadIdx.x;
    if (i < N_NODES) deg[i] = 0;
}
__global__ void hist_kernel(const void* __restrict__ ei, int* __restrict__ deg) {
    int e = blockIdx.x * blockDim.x + threadIdx.x;
    if (e >= N_EDGES) return;
    atomicAdd(&deg[load_idx(ei, (long long)N_EDGES + e)], 1);
}
__global__ void scanA_kernel(const int* __restrict__ deg, int* __restrict__ blocksum) {
    __shared__ int red[256];
    const int t = threadIdx.x;
    const int base = blockIdx.x * SCAN_ITEMS;
    int s = 0;
#pragma unroll
    for (int j = 0; j < 4; j++) {
        int i = base + t + j * 256;
        if (i < N_NODES) s += deg[i];
    }
    red[t] = s;
    __syncthreads();
    for (int off = 128; off > 0; off >>= 1) {
        if (t < off) red[t] += red[t + off];
        __syncthreads();
    }
    if (t == 0) blocksum[blockIdx.x] = red[0];
}
__global__ void scanB_kernel(const int* __restrict__ blocksum,
                             int* __restrict__ blockoff, int* __restrict__ rowptr) {
    __shared__ int v[128];
    const int t = threadIdx.x;
    v[t] = (t < SCAN_BLOCKS) ? blocksum[t] : 0;
    __syncthreads();
    int mine = v[t];
    for (int off = 1; off < 128; off <<= 1) {
        int tmp = (t >= off) ? v[t - off] : 0;
        __syncthreads();
        v[t] += tmp;
        __syncthreads();
    }
    if (t < SCAN_BLOCKS) blockoff[t] = v[t] - mine;
    if (t == 127) rowptr[N_NODES] = v[127];
}
__global__ void scanC_kernel(const int* __restrict__ deg, const int* __restrict__ blockoff,
                             int* __restrict__ rowptr, int* __restrict__ cursor) {
    __shared__ int ts[256];
    const int t = threadIdx.x;
    const int base = blockIdx.x * SCAN_ITEMS + t * 4;
    int d0 = 0, d1 = 0, d2 = 0, d3 = 0;
    if (base + 0 < N_NODES) d0 = deg[base + 0];
    if (base + 1 < N_NODES) d1 = deg[base + 1];
    if (base + 2 < N_NODES) d2 = deg[base + 2];
    if (base + 3 < N_NODES) d3 = deg[base + 3];
    int tot = d0 + d1 + d2 + d3;
    ts[t] = tot;
    __syncthreads();
    for (int off = 1; off < 256; off <<= 1) {
        int tmp = (t >= off) ? ts[t - off] : 0;
        __syncthreads();
        ts[t] += tmp;
        __syncthreads();
    }
    int run = blockoff[blockIdx.x] + ts[t] - tot;
    if (base + 0 < N_NODES) { rowptr[base + 0] = run; cursor[base + 0] = run; run += d0; }
    if (base + 1 < N_NODES) { rowptr[base + 1] = run; cursor[base + 1] = run; run += d1; }
    if (base + 2 < N_NODES) { rowptr[base + 2] = run; cursor[base + 2] = run; run += d2; }
    if (base + 3 < N_NODES) { rowptr[base + 3] = run; cursor[base + 3] = run; run += d3; }
}
__global__ void fill_kernel(const void* __restrict__ ei,
                            int* __restrict__ cursor, int* __restrict__ csrsrc) {
    int e = blockIdx.x * blockDim.x + threadIdx.x;
    if (e >= N_EDGES) return;
    int s = load_idx(ei, e);
    int d = load_idx(ei, (long long)N_EDGES + e);
    csrsrc[atomicAdd(&cursor[d], 1)] = s;
}

// ===========================================================================
// GIN aggregation (gather): out[n] = x[n] + sum_{e in CSR[n]} x[src[e]]
// ===========================================================================
__global__ void agg_kernel(const float* __restrict__ x, float* __restrict__ out,
                           const int* __restrict__ rowptr, const int* __restrict__ csrsrc) {
    long long t = (long long)blockIdx.x * blockDim.x + threadIdx.x;
    int n = (int)(t >> 5);
    if (n >= N_NODES) return;
    const int lane = (int)(t & 31);
    const int beg = rowptr[n];
    const int end = rowptr[n + 1];
    float4 acc = ((const float4*)(x + (size_t)n * FEAT))[lane];
    for (int base = beg; base < end; base += 32) {
        const int cnt = min(32, end - base);
        int sid = (base + lane < end) ? csrsrc[base + lane] : 0;
#pragma unroll 4
        for (int j = 0; j < cnt; j++) {
            int s = __shfl_sync(0xffffffffu, sid, j);
            float4 v = ((const float4*)(x + (size_t)s * FEAT))[lane];
            acc.x += v.x; acc.y += v.y; acc.z += v.z; acc.w += v.w;
        }
    }
    ((float4*)(out + (size_t)n * FEAT))[lane] = acc;
}

// ===========================================================================
// Persistent bf16-split tensor-core GEMM (HMMA):
//   C[m][n] = relu( sum_k A[m][k]*W[n][k] + bias[n] )
// Grid = 148 persistent blocks; each converts W once, loops over M-tiles.
// A tile prefetched fp32 via cp.async into smem stage (overlaps MMA), then
// split-converted. acc += Ahi*Whi + Ahi*Wlo + Alo*Whi (fp32 accum).
// ===========================================================================
#define SAB 136                          // bf16 elems per smem row (272B)
#define TILE_B (128 * SAB * 2)           // 34816 B per split tile
#define STG_F  132                       // stage row stride in floats (528B)
#define SMP_BIAS 0
#define SMP_WHI  512
#define SMP_WLO  (512 + TILE_B)
#define SMP_AHI  (512 + 2 * TILE_B)
#define SMP_ALO  (512 + 3 * TILE_B)
#define SMP_STG  (512 + 4 * TILE_B)      // 128 * 528 = 67584 B
#define SMP_TOTAL (SMP_STG + 128 * STG_F * 4)  // 207,360 B
#define GEMM_GRID 148

__global__ void __launch_bounds__(256)
gemm_mma_kernel(const float* __restrict__ A, const float* __restrict__ W,
                const float* __restrict__ bias, float* __restrict__ C, int M) {
    extern __shared__ char smem[];
    const uint32_t sb = smem_u32(smem);
    const int tid = threadIdx.x;
    const int lane = tid & 31;
    const int wid = tid >> 5;
    const int numTiles = (M + 127) >> 7;

    float* stg = (float*)(smem + SMP_STG);

    // ---- prefetch first A tile ----
    int tile = blockIdx.x;
    if (tile < numTiles) {
        const int row0 = tile << 7;
#pragma unroll
        for (int j = 0; j < 16; j++) {
            const int i = tid + j * 256;       // chunk id: 32 x 16B per row
            const int r = i >> 5, c16 = i & 31;
            if (row0 + r < M)
                cp16(sb + SMP_STG + (uint32_t)(r * STG_F + c16 * 4) * 4,
                     A + (size_t)(row0 + r) * FEAT + c16 * 4);
        }
    }
    CP_COMMIT();

    // ---- bias + one-time W split-convert ----
    if (tid < 128) ((float*)(smem + SMP_BIAS))[tid] = bias[tid];
    {
        const int r = tid >> 1;
        const int half = tid & 1;
        const float4* wrow = (const float4*)(W + (size_t)r * FEAT);
#pragma unroll
        for (int j = 0; j < 16; j++) {
            const int col = half * 64 + j * 4;
            const uint32_t off = (uint32_t)(r * SAB + col) * 2;
            float4 vw = wrow[half * 16 + j];
            float g0 = __bfloat162float(__float2bfloat16_rn(vw.x));
            float g1 = __bfloat162float(__float2bfloat16_rn(vw.y));
            float g2 = __bfloat162float(__float2bfloat16_rn(vw.z));
            float g3 = __bfloat162float(__float2bfloat16_rn(vw.w));
            *(uint2*)(smem + SMP_WHI + off) = make_uint2(pack_bf16(g0, g1), pack_bf16(g2, g3));
            *(uint2*)(smem + SMP_WLO + off) =
                make_uint2(pack_bf16(vw.x - g0, vw.y - g1), pack_bf16(vw.z - g2, vw.w - g3));
        }
    }

    // warp tiling constants
    const int m0 = (wid & 3) * 32;
    const int n0 = (wid >> 2) * 64;
    const int g = lane >> 3, rr = lane & 7;
    uint32_t aH0[2], aL0[2], bH0[4], bL0[4];
#pragma unroll
    for (int mb = 0; mb < 2; mb++) {
        const uint32_t o = (uint32_t)((m0 + mb * 16 + (g & 1) * 8 + rr) * SAB + (g >> 1) * 8) * 2;
        aH0[mb] = sb + SMP_AHI + o;
        aL0[mb] = sb + SMP_ALO + o;
    }
#pragma unroll
    for (int p = 0; p < 4; p++) {
        const uint32_t o = (uint32_t)((n0 + p * 16 + (g >> 1) * 8 + rr) * SAB + (g & 1) * 8) * 2;
        bH0[p] = sb + SMP_WHI + o;
        bL0[p] = sb + SMP_WLO + o;
    }
    const float* bs = (const float*)(smem + SMP_BIAS);

    // ---- persistent tile loop ----
    for (; tile < numTiles; tile += GEMM_GRID) {
        const int row0 = tile << 7;

        CP_WAIT0();
        __syncthreads();   // stage ready; all warps done with splitA from prev tile

        // convert stage -> split A
        {
            const int r = tid >> 1;
            const int half = tid & 1;
            const bool in = (row0 + r < M);
            const float* srow = stg + r * STG_F + half * 64;
#pragma unroll
            for (int j = 0; j < 16; j++) {
                const int col = half * 64 + j * 4;
                const uint32_t off = (uint32_t)(r * SAB + col) * 2;
                float4 va = in ? *(const float4*)(srow + j * 4) : make_float4(0.f, 0.f, 0.f, 0.f);
                float h0 = __bfloat162float(__float2bfloat16_rn(va.x));
                float h1 = __bfloat162float(__float2bfloat16_rn(va.y));
                float h2 = __bfloat162float(__float2bfloat16_rn(va.z));
                float h3 = __bfloat162float(__float2bfloat16_rn(va.w));
                *(uint2*)(smem + SMP_AHI + off) = make_uint2(pack_bf16(h0, h1), pack_bf16(h2, h3));
                *(uint2*)(smem + SMP_ALO + off) =
                    make_uint2(pack_bf16(va.x - h0, va.y - h1), pack_bf16(va.z - h2, va.w - h3));
            }
        }
        __syncthreads();

        // prefetch next tile (overlaps MMA below)
        const int nt = tile + GEMM_GRID;
        if (nt < numTiles) {
            const int nrow0 = nt << 7;
#pragma unroll
            for (int j = 0; j < 16; j++) {
                const int i = tid + j * 256;
                const int r = i >> 5, c16 = i & 31;
                if (nrow0 + r < M)
                    cp16(sb + SMP_STG + (uint32_t)(r * STG_F + c16 * 4) * 4,
                         A + (size_t)(nrow0 + r) * FEAT + c16 * 4);
            }
        }
        CP_COMMIT();

        // ---- MMA ----
        float acc[2][8][4];
#pragma unroll
        for (int mb = 0; mb < 2; mb++)
#pragma unroll
            for (int o = 0; o < 8; o++)
#pragma unroll
                for (int q = 0; q < 4; q++) acc[mb][o][q] = 0.f;

        uint32_t aH[2] = {aH0[0], aH0[1]}, aL[2] = {aL0[0], aL0[1]};
        uint32_t bH[4] = {bH0[0], bH0[1], bH0[2], bH0[3]};
        uint32_t bL[4] = {bL0[0], bL0[1], bL0[2], bL0[3]};
#pragma unroll
        for (int kk = 0; kk < 8; kk++) {
            uint32_t ah[2][4], al[2][4], bb[4][4];
            ldsm_x4(ah[0], aH[0]); ldsm_x4(ah[1], aH[1]);
            ldsm_x4(al[0], aL[0]); ldsm_x4(al[1], aL[1]);
            ldsm_x4(bb[0], bH[0]); ldsm_x4(bb[1], bH[1]);
            ldsm_x4(bb[2], bH[2]); ldsm_x4(bb[3], bH[3]);
#pragma unroll
            for (int mb = 0; mb < 2; mb++)
#pragma unroll
                for (int o = 0; o < 8; o++) {
                    const uint32_t* b = &bb[o >> 1][(o & 1) * 2];
                    mma_bf16(acc[mb][o], ah[mb], b);   // hi*hi
                    mma_bf16(acc[mb][o], al[mb], b);   // lo*hi
                }
            ldsm_x4(bb[0], bL[0]); ldsm_x4(bb[1], bL[1]);
            ldsm_x4(bb[2], bL[2]); ldsm_x4(bb[3], bL[3]);
#pragma unroll
            for (int mb = 0; mb < 2; mb++)
#pragma unroll
                for (int o = 0; o < 8; o++)
                    mma_bf16(acc[mb][o], ah[mb], &bb[o >> 1][(o & 1) * 2]);  // hi*lo
#pragma unroll
            for (int i = 0; i < 2; i++) { aH[i] += 32; aL[i] += 32; }
#pragma unroll
            for (int i = 0; i < 4; i++) { bH[i] += 32; bL[i] += 32; }
        }

        // ---- epilogue ----
#pragma unroll
        for (int mb = 0; mb < 2; mb++) {
            const int rbase = row0 + m0 + mb * 16 + (lane >> 2);
#pragma unroll
            for (int o = 0; o < 8; o++) {
                const int col = n0 + o * 8 + (lane & 3) * 2;
                const float b0 = bs[col], b1 = bs[col + 1];
                if (rbase < M) {
                    float2 v = make_float2(fmaxf(acc[mb][o][0] + b0, 0.f),
                                           fmaxf(acc[mb][o][1] + b1, 0.f));
                    *(float2*)(C + (size_t)rbase * FEAT + col) = v;
                }
                if (rbase + 8 < M) {
                    float2 v = make_float2(fmaxf(acc[mb][o][2] + b0, 0.f),
                                           fmaxf(acc[mb][o][3] + b1, 0.f));
                    *(float2*)(C + (size_t)(rbase + 8) * FEAT + col) = v;
                }
            }
        }
    }
}

// ===========================================================================
// Global mean pool per graph (batch sorted -> binary search)
// ===========================================================================
__global__ void pool_kernel(const float* __restrict__ h, const void* __restrict__ batch,
                            float* __restrict__ out_pool) {
    const int g = blockIdx.x;
    const int c = threadIdx.x;
    const int is64 = g_idx64;
    const long long* b64 = (const long long*)batch;
    const int* b32 = (const int*)batch;

    int lo = 0, hi = N_NODES;
    while (lo < hi) {
        int mid = (lo + hi) >> 1;
        long long v = is64 ? b64[mid] : (long long)b32[mid];
        if (v < (long long)g) lo = mid + 1; else hi = mid;
    }
    const int start = lo;
    hi = N_NODES;
    while (lo < hi) {
        int mid = (lo + hi) >> 1;
        long long v = is64 ? b64[mid] : (long long)b32[mid];
        if (v < (long long)g + 1) lo = mid + 1; else hi = mid;
    }
    const int end = lo;

    float s = 0.f;
    for (int r = start; r < end; r++) s += h[(size_t)r * FEAT + c];
    out_pool[g * FEAT + c] = s / fmaxf((float)(end - start), 1.f);
}

// ===========================================================================
extern "C" void kernel_launch(void* const* d_in, const int* in_sizes, int n_in,
                              void* d_out, int out_size) {
    const float* x   = (const float*)d_in[0];
    const void*  ei  = d_in[1];
    const void*  bat = d_in[2];
    const float* W1 = (const float*)d_in[3];
    const float* b1 = (const float*)d_in[4];
    const float* W2 = (const float*)d_in[5];
    const float* b2 = (const float*)d_in[6];
    const float* W3 = (const float*)d_in[7];
    const float* b3 = (const float*)d_in[8];
    const float* W4 = (const float*)d_in[9];
    const float* b4 = (const float*)d_in[10];

    float* out      = (float*)d_out;
    float* out_pool = out;
    float* out_h    = out + N_GRAPHS * FEAT;

    float *bufA, *bufB;
    int *deg, *rowptr, *cursor, *csrsrc, *blocksum, *blockoff;
    cudaGetSymbolAddress((void**)&bufA, g_bufA);
    cudaGetSymbolAddress((void**)&bufB, g_bufB);
    cudaGetSymbolAddress((void**)&deg, g_deg);
    cudaGetSymbolAddress((void**)&rowptr, g_rowptr);
    cudaGetSymbolAddress((void**)&cursor, g_cursor);
    cudaGetSymbolAddress((void**)&csrsrc, g_csrsrc);
    cudaGetSymbolAddress((void**)&blocksum, g_blocksum);
    cudaGetSymbolAddress((void**)&blockoff, g_blockoff);

    cudaFuncSetAttribute(gemm_mma_kernel,
                         cudaFuncAttributeMaxDynamicSharedMemorySize, SMP_TOTAL);

    const int edge_blocks = (N_EDGES + 255) / 256;
    const int node_blocks = (N_NODES + 255) / 256;
    const long long athreads = (long long)N_NODES * 32;
    const int agg_blocks = (int)((athreads + 255) / 256);

    // ---- CSR build ----
    detect_kernel<<<1, 32>>>((const int*)ei);
    zero_deg_kernel<<<node_blocks, 256>>>(deg);
    hist_kernel<<<edge_blocks, 256>>>(ei, deg);
    scanA_kernel<<<SCAN_BLOCKS, 256>>>(deg, blocksum);
    scanB_kernel<<<1, 128>>>(blocksum, blockoff, rowptr);
    scanC_kernel<<<SCAN_BLOCKS, 256>>>(deg, blockoff, rowptr, cursor);
    fill_kernel<<<edge_blocks, 256>>>(ei, cursor, csrsrc);

    // ---- Layer 1 ----
    agg_kernel<<<agg_blocks, 256>>>(x, bufA, rowptr, csrsrc);
    gemm_mma_kernel<<<GEMM_GRID, 256, SMP_TOTAL>>>(bufA, W1, b1, bufB, N_NODES);
    gemm_mma_kernel<<<GEMM_GRID, 256, SMP_TOTAL>>>(bufB, W2, b2, bufA, N_NODES);

    // ---- Layer 2 ----
    agg_kernel<<<agg_blocks, 256>>>(bufA, bufB, rowptr, csrsrc);
    gemm_mma_kernel<<<GEMM_GRID, 256, SMP_TOTAL>>>(bufB, W3, b3, bufA, N_NODES);
    gemm_mma_kernel<<<GEMM_GRID, 256, SMP_TOTAL>>>(bufA, W4, b4, out_h, N_NODES);

    // ---- Global mean pool ----
    pool_kernel<<<N_GRAPHS, FEAT>>>(out_h, bat, out_pool);
}

// round 8
// speedup vs baseline: 3.8096x; 1.0627x over previous
#include <cuda_runtime.h>
#include <cuda_bf16.h>
#include <cstdint>

#define N_NODES 100000
#define N_EDGES 1600000
#define FEAT 128
#define N_GRAPHS 100

#define SCAN_ITEMS 1024
#define SCAN_BLOCKS ((N_NODES + SCAN_ITEMS - 1) / SCAN_ITEMS)  // 98

// Scratch (allocation-free rule: __device__ globals)
__device__ float g_bufA[(size_t)N_NODES * FEAT];
__device__ float g_bufB[(size_t)N_NODES * FEAT];
__device__ int   g_deg[N_NODES];
__device__ int   g_rowptr[N_NODES + 1];
__device__ int   g_cursor[N_NODES];
__device__ int   g_csrsrc[N_EDGES];
__device__ int   g_blocksum[SCAN_BLOCKS];
__device__ int   g_blockoff[SCAN_BLOCKS];
__device__ int   g_idx64;

// ===========================================================================
// Helpers
// ===========================================================================
__device__ __forceinline__ uint32_t smem_u32(const void* p) {
    uint32_t a;
    asm("{ .reg .u64 t; cvta.to.shared.u64 t, %1; cvt.u32.u64 %0, t; }" : "=r"(a) : "l"(p));
    return a;
}
__device__ __forceinline__ uint32_t pack_bf16(float a, float b) {
    uint32_t r;
    asm("cvt.rn.bf16x2.f32 %0, %1, %2;" : "=r"(r) : "f"(b), "f"(a));
    return r;
}
__device__ __forceinline__ void ldsm_x4(uint32_t* r, uint32_t addr) {
    asm volatile("ldmatrix.sync.aligned.m8n8.x4.shared.b16 {%0,%1,%2,%3}, [%4];"
        : "=r"(r[0]), "=r"(r[1]), "=r"(r[2]), "=r"(r[3]) : "r"(addr));
}
__device__ __forceinline__ void mma_bf16(float* c, const uint32_t* a, const uint32_t* b) {
    asm volatile("mma.sync.aligned.m16n8k16.row.col.f32.bf16.bf16.f32 "
        "{%0,%1,%2,%3}, {%4,%5,%6,%7}, {%8,%9}, {%0,%1,%2,%3};"
        : "+f"(c[0]), "+f"(c[1]), "+f"(c[2]), "+f"(c[3])
        : "r"(a[0]), "r"(a[1]), "r"(a[2]), "r"(a[3]), "r"(b[0]), "r"(b[1]));
}
__device__ __forceinline__ void cp16(uint32_t saddr, const void* gptr) {
    asm volatile("cp.async.cg.shared.global [%0], [%1], 16;" :: "r"(saddr), "l"(gptr));
}
#define CP_COMMIT() asm volatile("cp.async.commit_group;" ::: "memory")
#define CP_WAIT0()  asm volatile("cp.async.wait_group 0;" ::: "memory")

// ===========================================================================
// Index dtype detector (int64 little-endian => odd words zero). 1 warp.
// ===========================================================================
__global__ void detect_kernel(const int* __restrict__ ei_words) {
    const int lane = threadIdx.x;
    int ok = 1;
#pragma unroll
    for (int j = 0; j < 16; j++) {
        int i = j * 32 + lane;
        int lo = ei_words[2 * i];
        int hi = ei_words[2 * i + 1];
        if (hi != 0 || lo < 0 || lo >= N_NODES) ok = 0;
    }
    int all = __all_sync(0xffffffffu, ok);
    if (lane == 0) g_idx64 = all;
}
__device__ __forceinline__ int load_idx(const void* p, long long i) {
    return g_idx64 ? (int)((const long long*)p)[i] : ((const int*)p)[i];
}

// ===========================================================================
// CSR build
// ===========================================================================
__global__ void zero_deg_kernel(int* __restrict__ deg) {
    int i = blockIdx.x * blockDim.x + threadIdx.x;
    if (i < N_NODES) deg[i] = 0;
}
__global__ void hist_kernel(const void* __restrict__ ei, int* __restrict__ deg) {
    int e = blockIdx.x * blockDim.x + threadIdx.x;
    if (e >= N_EDGES) return;
    atomicAdd(&deg[load_idx(ei, (long long)N_EDGES + e)], 1);
}
__global__ void scanA_kernel(const int* __restrict__ deg, int* __restrict__ blocksum) {
    __shared__ int red[256];
    const int t = threadIdx.x;
    const int base = blockIdx.x * SCAN_ITEMS;
    int s = 0;
#pragma unroll
    for (int j = 0; j < 4; j++) {
        int i = base + t + j * 256;
        if (i < N_NODES) s += deg[i];
    }
    red[t] = s;
    __syncthreads();
    for (int off = 128; off > 0; off >>= 1) {
        if (t < off) red[t] += red[t + off];
        __syncthreads();
    }
    if (t == 0) blocksum[blockIdx.x] = red[0];
}
__global__ void scanB_kernel(const int* __restrict__ blocksum,
                             int* __restrict__ blockoff, int* __restrict__ rowptr) {
    __shared__ int v[128];
    const int t = threadIdx.x;
    v[t] = (t < SCAN_BLOCKS) ? blocksum[t] : 0;
    __syncthreads();
    int mine = v[t];
    for (int off = 1; off < 128; off <<= 1) {
        int tmp = (t >= off) ? v[t - off] : 0;
        __syncthreads();
        v[t] += tmp;
        __syncthreads();
    }
    if (t < SCAN_BLOCKS) blockoff[t] = v[t] - mine;
    if (t == 127) rowptr[N_NODES] = v[127];
}
__global__ void scanC_kernel(const int* __restrict__ deg, const int* __restrict__ blockoff,
                             int* __restrict__ rowptr, int* __restrict__ cursor) {
    __shared__ int ts[256];
    const int t = threadIdx.x;
    const int base = blockIdx.x * SCAN_ITEMS + t * 4;
    int d0 = 0, d1 = 0, d2 = 0, d3 = 0;
    if (base + 0 < N_NODES) d0 = deg[base + 0];
    if (base + 1 < N_NODES) d1 = deg[base + 1];
    if (base + 2 < N_NODES) d2 = deg[base + 2];
    if (base + 3 < N_NODES) d3 = deg[base + 3];
    int tot = d0 + d1 + d2 + d3;
    ts[t] = tot;
    __syncthreads();
    for (int off = 1; off < 256; off <<= 1) {
        int tmp = (t >= off) ? ts[t - off] : 0;
        __syncthreads();
        ts[t] += tmp;
        __syncthreads();
    }
    int run = blockoff[blockIdx.x] + ts[t] - tot;
    if (base + 0 < N_NODES) { rowptr[base + 0] = run; cursor[base + 0] = run; run += d0; }
    if (base + 1 < N_NODES) { rowptr[base + 1] = run; cursor[base + 1] = run; run += d1; }
    if (base + 2 < N_NODES) { rowptr[base + 2] = run; cursor[base + 2] = run; run += d2; }
    if (base + 3 < N_NODES) { rowptr[base + 3] = run; cursor[base + 3] = run; run += d3; }
}
__global__ void fill_kernel(const void* __restrict__ ei,
                            int* __restrict__ cursor, int* __restrict__ csrsrc) {
    int e = blockIdx.x * blockDim.x + threadIdx.x;
    if (e >= N_EDGES) return;
    int s = load_idx(ei, e);
    int d = load_idx(ei, (long long)N_EDGES + e);
    csrsrc[atomicAdd(&cursor[d], 1)] = s;
}

// ===========================================================================
// GIN aggregation (gather): out[n] = x[n] + sum_{e in CSR[n]} x[src[e]]
// ===========================================================================
__global__ void agg_kernel(const float* __restrict__ x, float* __restrict__ out,
                           const int* __restrict__ rowptr, const int* __restrict__ csrsrc) {
    long long t = (long long)blockIdx.x * blockDim.x + threadIdx.x;
    int n = (int)(t >> 5);
    if (n >= N_NODES) return;
    const int lane = (int)(t & 31);
    const int beg = rowptr[n];
    const int end = rowptr[n + 1];
    float4 acc = ((const float4*)(x + (size_t)n * FEAT))[lane];
    for (int base = beg; base < end; base += 32) {
        const int cnt = min(32, end - base);
        int sid = (base + lane < end) ? csrsrc[base + lane] : 0;
#pragma unroll 4
        for (int j = 0; j < cnt; j++) {
            int s = __shfl_sync(0xffffffffu, sid, j);
            float4 v = ((const float4*)(x + (size_t)s * FEAT))[lane];
            acc.x += v.x; acc.y += v.y; acc.z += v.z; acc.w += v.w;
        }
    }
    ((float4*)(out + (size_t)n * FEAT))[lane] = acc;
}

// ===========================================================================
// Fused persistent MLP kernel (two bf16-split HMMA GEMMs, h1 never leaves SM):
//   C = relu( relu(A@W1^T + b1) @ W2^T + b2 )
// M-tile 64, 8 warps = 2(M) x 4(N), warp tile 32x32.
// W1,W2 split-converted once per block. A tile: cp.async stage -> split bf16.
// GEMM1 epilogue packs h1 (bias+relu, hi/lo bf16) back into the A buffers.
// ===========================================================================
#define SAB 136                            // bf16 elems per smem row (272B)
#define WTILE_B (128 * SAB * 2)            // 34816 B  (full 128-row W tile)
#define ATILE_B (64 * SAB * 2)             // 17408 B  (64-row A tile)
#define STG_F   132                        // stage row stride (floats)
#define SMF_B1   0
#define SMF_B2   512
#define SMF_W1H  1024
#define SMF_W1L  (SMF_W1H + WTILE_B)
#define SMF_W2H  (SMF_W1H + 2 * WTILE_B)
#define SMF_W2L  (SMF_W1H + 3 * WTILE_B)
#define SMF_AH   (SMF_W1H + 4 * WTILE_B)   // 140288
#define SMF_AL   (SMF_AH + ATILE_B)        // 157696
#define SMF_STG  (SMF_AL + ATILE_B)        // 175104
#define SMF_TOTAL (SMF_STG + 64 * STG_F * 4)  // 208896 B
#define GEMM_GRID 148

__global__ void __launch_bounds__(256)
mlp_fused_kernel(const float* __restrict__ A,
                 const float* __restrict__ W1, const float* __restrict__ b1,
                 const float* __restrict__ W2, const float* __restrict__ b2,
                 float* __restrict__ C, int M) {
    extern __shared__ char smem[];
    const uint32_t sb = smem_u32(smem);
    const int tid = threadIdx.x;
    const int lane = tid & 31;
    const int wid = tid >> 5;
    const int numTiles = (M + 63) >> 6;

    float* stg = (float*)(smem + SMF_STG);

    // ---- prefetch first A tile (64 rows x 128 f32) ----
    int tile = blockIdx.x;
    if (tile < numTiles) {
        const int row0 = tile << 6;
#pragma unroll
        for (int j = 0; j < 8; j++) {
            const int i = tid + j * 256;        // 64 rows x 32 chunks of 16B
            const int r = i >> 5, c16 = i & 31;
            if (row0 + r < M)
                cp16(sb + SMF_STG + (uint32_t)(r * STG_F + c16 * 4) * 4,
                     A + (size_t)(row0 + r) * FEAT + c16 * 4);
        }
    }
    CP_COMMIT();

    // ---- biases + one-time W1/W2 split-convert ----
    if (tid < 128) ((float*)(smem + SMF_B1))[tid] = b1[tid];
    else           ((float*)(smem + SMF_B2))[tid - 128] = b2[tid - 128];
    {
        const int r = tid >> 1;
        const int half = tid & 1;
        const float4* w1row = (const float4*)(W1 + (size_t)r * FEAT);
        const float4* w2row = (const float4*)(W2 + (size_t)r * FEAT);
#pragma unroll
        for (int j = 0; j < 16; j++) {
            const int col = half * 64 + j * 4;
            const uint32_t off = (uint32_t)(r * SAB + col) * 2;
            float4 v1 = w1row[half * 16 + j];
            float a0 = __bfloat162float(__float2bfloat16_rn(v1.x));
            float a1 = __bfloat162float(__float2bfloat16_rn(v1.y));
            float a2 = __bfloat162float(__float2bfloat16_rn(v1.z));
            float a3 = __bfloat162float(__float2bfloat16_rn(v1.w));
            *(uint2*)(smem + SMF_W1H + off) = make_uint2(pack_bf16(a0, a1), pack_bf16(a2, a3));
            *(uint2*)(smem + SMF_W1L + off) =
                make_uint2(pack_bf16(v1.x - a0, v1.y - a1), pack_bf16(v1.z - a2, v1.w - a3));
            float4 v2 = w2row[half * 16 + j];
            float c0 = __bfloat162float(__float2bfloat16_rn(v2.x));
            float c1 = __bfloat162float(__float2bfloat16_rn(v2.y));
            float c2 = __bfloat162float(__float2bfloat16_rn(v2.z));
            float c3 = __bfloat162float(__float2bfloat16_rn(v2.w));
            *(uint2*)(smem + SMF_W2H + off) = make_uint2(pack_bf16(c0, c1), pack_bf16(c2, c3));
            *(uint2*)(smem + SMF_W2L + off) =
                make_uint2(pack_bf16(v2.x - c0, v2.y - c1), pack_bf16(v2.z - c2, v2.w - c3));
        }
    }

    // ---- warp tiling constants ----
    const int m0 = (wid & 1) * 32;       // 2 warps along M (64 rows)
    const int n0 = (wid >> 1) * 32;      // 4 warps along N (128 cols)
    const int g = lane >> 3, rr = lane & 7;
    uint32_t aH0[2], aL0[2], b1H[2], b1L[2], b2H[2], b2L[2];
#pragma unroll
    for (int mb = 0; mb < 2; mb++) {
        const uint32_t o = (uint32_t)((m0 + mb * 16 + (g & 1) * 8 + rr) * SAB + (g >> 1) * 8) * 2;
        aH0[mb] = sb + SMF_AH + o;
        aL0[mb] = sb + SMF_AL + o;
    }
#pragma unroll
    for (int p = 0; p < 2; p++) {
        const uint32_t o = (uint32_t)((n0 + p * 16 + (g >> 1) * 8 + rr) * SAB + (g & 1) * 8) * 2;
        b1H[p] = sb + SMF_W1H + o;
        b1L[p] = sb + SMF_W1L + o;
        b2H[p] = sb + SMF_W2H + o;
        b2L[p] = sb + SMF_W2L + o;
    }
    const float* bs1 = (const float*)(smem + SMF_B1);
    const float* bs2 = (const float*)(smem + SMF_B2);

    // ---- persistent tile loop ----
    for (; tile < numTiles; tile += GEMM_GRID) {
        const int row0 = tile << 6;

        CP_WAIT0();
        __syncthreads();

        // convert stage -> split A (64 rows)
        {
            const int r = tid >> 2;            // 0..63
            const int q = tid & 3;             // 32 cols each
            const bool in = (row0 + r < M);
            const float* srow = stg + r * STG_F + q * 32;
#pragma unroll
            for (int j = 0; j < 8; j++) {
                const int col = q * 32 + j * 4;
                const uint32_t off = (uint32_t)(r * SAB + col) * 2;
                float4 va = in ? *(const float4*)(srow + j * 4) : make_float4(0.f, 0.f, 0.f, 0.f);
                float h0 = __bfloat162float(__float2bfloat16_rn(va.x));
                float h1 = __bfloat162float(__float2bfloat16_rn(va.y));
                float h2 = __bfloat162float(__float2bfloat16_rn(va.z));
                float h3 = __bfloat162float(__float2bfloat16_rn(va.w));
                *(uint2*)(smem + SMF_AH + off) = make_uint2(pack_bf16(h0, h1), pack_bf16(h2, h3));
                *(uint2*)(smem + SMF_AL + off) =
                    make_uint2(pack_bf16(va.x - h0, va.y - h1), pack_bf16(va.z - h2, va.w - h3));
            }
        }
        __syncthreads();

        // prefetch next tile (overlaps both GEMMs)
        const int nt = tile + GEMM_GRID;
        if (nt < numTiles) {
            const int nrow0 = nt << 6;
#pragma unroll
            for (int j = 0; j < 8; j++) {
                const int i = tid + j * 256;
                const int r = i >> 5, c16 = i & 31;
                if (nrow0 + r < M)
                    cp16(sb + SMF_STG + (uint32_t)(r * STG_F + c16 * 4) * 4,
                         A + (size_t)(nrow0 + r) * FEAT + c16 * 4);
            }
        }
        CP_COMMIT();

        // ================= GEMM1: acc = A @ W1^T =================
        float acc[2][4][4];
#pragma unroll
        for (int mb = 0; mb < 2; mb++)
#pragma unroll
            for (int o = 0; o < 4; o++)
#pragma unroll
                for (int q = 0; q < 4; q++) acc[mb][o][q] = 0.f;
        {
            uint32_t aH[2] = {aH0[0], aH0[1]}, aL[2] = {aL0[0], aL0[1]};
            uint32_t bH[2] = {b1H[0], b1H[1]}, bL[2] = {b1L[0], b1L[1]};
#pragma unroll
            for (int kk = 0; kk < 8; kk++) {
                uint32_t ah[2][4], al[2][4], bb[2][4];
                ldsm_x4(ah[0], aH[0]); ldsm_x4(ah[1], aH[1]);
                ldsm_x4(al[0], aL[0]); ldsm_x4(al[1], aL[1]);
                ldsm_x4(bb[0], bH[0]); ldsm_x4(bb[1], bH[1]);
#pragma unroll
                for (int mb = 0; mb < 2; mb++)
#pragma unroll
                    for (int o = 0; o < 4; o++) {
                        const uint32_t* b = &bb[o >> 1][(o & 1) * 2];
                        mma_bf16(acc[mb][o], ah[mb], b);
                        mma_bf16(acc[mb][o], al[mb], b);
                    }
                ldsm_x4(bb[0], bL[0]); ldsm_x4(bb[1], bL[1]);
#pragma unroll
                for (int mb = 0; mb < 2; mb++)
#pragma unroll
                    for (int o = 0; o < 4; o++)
                        mma_bf16(acc[mb][o], ah[mb], &bb[o >> 1][(o & 1) * 2]);
#pragma unroll
                for (int i = 0; i < 2; i++) { aH[i] += 32; aL[i] += 32; bH[i] += 32; bL[i] += 32; }
            }
        }
        __syncthreads();   // all warps done reading A -> safe to overwrite with h1

        // ---- h1 = relu(acc + b1), split-pack into A buffers ----
#pragma unroll
        for (int mb = 0; mb < 2; mb++) {
            const int r0 = m0 + mb * 16 + (lane >> 2);
#pragma unroll
            for (int o = 0; o < 4; o++) {
                const int col = n0 + o * 8 + (lane & 3) * 2;
                const float c0 = bs1[col], c1 = bs1[col + 1];
                const uint32_t off0 = (uint32_t)(r0 * SAB + col) * 2;
                const uint32_t off8 = (uint32_t)((r0 + 8) * SAB + col) * 2;
                float v0 = fmaxf(acc[mb][o][0] + c0, 0.f);
                float v1 = fmaxf(acc[mb][o][1] + c1, 0.f);
                float h0 = __bfloat162float(__float2bfloat16_rn(v0));
                float h1 = __bfloat162float(__float2bfloat16_rn(v1));
                *(uint32_t*)(smem + SMF_AH + off0) = pack_bf16(h0, h1);
                *(uint32_t*)(smem + SMF_AL + off0) = pack_bf16(v0 - h0, v1 - h1);
                float v2 = fmaxf(acc[mb][o][2] + c0, 0.f);
                float v3 = fmaxf(acc[mb][o][3] + c1, 0.f);
                float h2 = __bfloat162float(__float2bfloat16_rn(v2));
                float h3 = __bfloat162float(__float2bfloat16_rn(v3));
                *(uint32_t*)(smem + SMF_AH + off8) = pack_bf16(h2, h3);
                *(uint32_t*)(smem + SMF_AL + off8) = pack_bf16(v2 - h2, v3 - h3);
            }
        }
        __syncthreads();

        // ================= GEMM2: acc = h1 @ W2^T =================
#pragma unroll
        for (int mb = 0; mb < 2; mb++)
#pragma unroll
            for (int o = 0; o < 4; o++)
#pragma unroll
                for (int q = 0; q < 4; q++) acc[mb][o][q] = 0.f;
        {
            uint32_t aH[2] = {aH0[0], aH0[1]}, aL[2] = {aL0[0], aL0[1]};
            uint32_t bH[2] = {b2H[0], b2H[1]}, bL[2] = {b2L[0], b2L[1]};
#pragma unroll
            for (int kk = 0; kk < 8; kk++) {
                uint32_t ah[2][4], al[2][4], bb[2][4];
                ldsm_x4(ah[0], aH[0]); ldsm_x4(ah[1], aH[1]);
                ldsm_x4(al[0], aL[0]); ldsm_x4(al[1], aL[1]);
                ldsm_x4(bb[0], bH[0]); ldsm_x4(bb[1], bH[1]);
#pragma unroll
                for (int mb = 0; mb < 2; mb++)
#pragma unroll
                    for (int o = 0; o < 4; o++) {
                        const uint32_t* b = &bb[o >> 1][(o & 1) * 2];
                        mma_bf16(acc[mb][o], ah[mb], b);
                        mma_bf16(acc[mb][o], al[mb], b);
                    }
                ldsm_x4(bb[0], bL[0]); ldsm_x4(bb[1], bL[1]);
#pragma unroll
                for (int mb = 0; mb < 2; mb++)
#pragma unroll
                    for (int o = 0; o < 4; o++)
                        mma_bf16(acc[mb][o], ah[mb], &bb[o >> 1][(o & 1) * 2]);
#pragma unroll
                for (int i = 0; i < 2; i++) { aH[i] += 32; aL[i] += 32; bH[i] += 32; bL[i] += 32; }
            }
        }
        __syncthreads();   // A buffers reused next iteration after convert

        // ---- final epilogue: relu(acc + b2) -> C ----
#pragma unroll
        for (int mb = 0; mb < 2; mb++) {
            const int rbase = row0 + m0 + mb * 16 + (lane >> 2);
#pragma unroll
            for (int o = 0; o < 4; o++) {
                const int col = n0 + o * 8 + (lane & 3) * 2;
                const float c0 = bs2[col], c1 = bs2[col + 1];
                if (rbase < M) {
                    float2 v = make_float2(fmaxf(acc[mb][o][0] + c0, 0.f),
                                           fmaxf(acc[mb][o][1] + c1, 0.f));
                    *(float2*)(C + (size_t)rbase * FEAT + col) = v;
                }
                if (rbase + 8 < M) {
                    float2 v = make_float2(fmaxf(acc[mb][o][2] + c0, 0.f),
                                           fmaxf(acc[mb][o][3] + c1, 0.f));
                    *(float2*)(C + (size_t)(rbase + 8) * FEAT + col) = v;
                }
            }
        }
    }
}

// ===========================================================================
// Global mean pool per graph (batch sorted -> binary search)
// ===========================================================================
__global__ void pool_kernel(const float* __restrict__ h, const void* __restrict__ batch,
                            float* __restrict__ out_pool) {
    const int g = blockIdx.x;
    const int c = threadIdx.x;
    const int is64 = g_idx64;
    const long long* b64 = (const long long*)batch;
    const int* b32 = (const int*)batch;

    int lo = 0, hi = N_NODES;
    while (lo < hi) {
        int mid = (lo + hi) >> 1;
        long long v = is64 ? b64[mid] : (long long)b32[mid];
        if (v < (long long)g) lo = mid + 1; else hi = mid;
    }
    const int start = lo;
    hi = N_NODES;
    while (lo < hi) {
        int mid = (lo + hi) >> 1;
        long long v = is64 ? b64[mid] : (long long)b32[mid];
        if (v < (long long)g + 1) lo = mid + 1; else hi = mid;
    }
    const int end = lo;

    float s = 0.f;
    for (int r = start; r < end; r++) s += h[(size_t)r * FEAT + c];
    out_pool[g * FEAT + c] = s / fmaxf((float)(end - start), 1.f);
}

// ===========================================================================
extern "C" void kernel_launch(void* const* d_in, const int* in_sizes, int n_in,
                              void* d_out, int out_size) {
    const float* x   = (const float*)d_in[0];
    const void*  ei  = d_in[1];
    const void*  bat = d_in[2];
    const float* W1 = (const float*)d_in[3];
    const float* b1 = (const float*)d_in[4];
    const float* W2 = (const float*)d_in[5];
    const float* b2 = (const float*)d_in[6];
    const float* W3 = (const float*)d_in[7];
    const float* b3 = (const float*)d_in[8];
    const float* W4 = (const float*)d_in[9];
    const float* b4 = (const float*)d_in[10];

    float* out      = (float*)d_out;
    float* out_pool = out;
    float* out_h    = out + N_GRAPHS * FEAT;

    float *bufA, *bufB;
    int *deg, *rowptr, *cursor, *csrsrc, *blocksum, *blockoff;
    cudaGetSymbolAddress((void**)&bufA, g_bufA);
    cudaGetSymbolAddress((void**)&bufB, g_bufB);
    cudaGetSymbolAddress((void**)&deg, g_deg);
    cudaGetSymbolAddress((void**)&rowptr, g_rowptr);
    cudaGetSymbolAddress((void**)&cursor, g_cursor);
    cudaGetSymbolAddress((void**)&csrsrc, g_csrsrc);
    cudaGetSymbolAddress((void**)&blocksum, g_blocksum);
    cudaGetSymbolAddress((void**)&blockoff, g_blockoff);

    cudaFuncSetAttribute(mlp_fused_kernel,
                         cudaFuncAttributeMaxDynamicSharedMemorySize, SMF_TOTAL);

    const int edge_blocks = (N_EDGES + 255) / 256;
    const int node_blocks = (N_NODES + 255) / 256;
    const long long athreads = (long long)N_NODES * 32;
    const int agg_blocks = (int)((athreads + 255) / 256);

    // ---- CSR build ----
    detect_kernel<<<1, 32>>>((const int*)ei);
    zero_deg_kernel<<<node_blocks, 256>>>(deg);
    hist_kernel<<<edge_blocks, 256>>>(ei, deg);
    scanA_kernel<<<SCAN_BLOCKS, 256>>>(deg, blocksum);
    scanB_kernel<<<1, 128>>>(blocksum, blockoff, rowptr);
    scanC_kernel<<<SCAN_BLOCKS, 256>>>(deg, blockoff, rowptr, cursor);
    fill_kernel<<<edge_blocks, 256>>>(ei, cursor, csrsrc);

    // ---- Layer 1 (agg + fused 2-GEMM MLP) ----
    agg_kernel<<<agg_blocks, 256>>>(x, bufA, rowptr, csrsrc);
    mlp_fused_kernel<<<GEMM_GRID, 256, SMF_TOTAL>>>(bufA, W1, b1, W2, b2, bufB, N_NODES);

    // ---- Layer 2 ----
    agg_kernel<<<agg_blocks, 256>>>(bufB, bufA, rowptr, csrsrc);
    mlp_fused_kernel<<<GEMM_GRID, 256, SMF_TOTAL>>>(bufA, W3, b3, W4, b4, out_h, N_NODES);

    // ---- Global mean pool ----
    pool_kernel<<<N_GRAPHS, FEAT>>>(out_h, bat, out_pool);
}